// round 13
// baseline (speedup 1.0000x reference)
#include <cuda_runtime.h>
#include <cuda_fp16.h>
#include <cstdint>

#define BATCH 2
#define EMB   1024
#define SEQ   2048
#define NH    16
#define DH    64
#define KDIM  1024
#define LOG2E 1.4426950408889634f
typedef unsigned short ushort_t;

#define WSZ ((size_t)KDIM * EMB)
#define XSZ ((size_t)BATCH * EMB * SEQ)
#define ESZ ((size_t)EMB * SEQ)

// ---------------- scratch ----------------------------------------------------
__device__ ushort_t g_wh[4 * WSZ];
__device__ ushort_t g_wl[4 * WSZ];
__device__ ushort_t g_xh[3 * XSZ];
__device__ ushort_t g_xl[3 * XSZ];
__device__ ushort_t g_ph[3 * XSZ];   // Q fp16-hi, K fp16, V fp16
__device__ ushort_t g_pl[3 * XSZ];   // Q fp16-lo, (unused), (unused)
__device__ ushort_t g_ath[XSZ];
__device__ ushort_t g_atl[XSZ];

// ---------------- helpers ----------------------------------------------------
__device__ __forceinline__ uint32_t smem_u32(const void* p) {
    uint32_t a;
    asm("{ .reg .u64 t; cvta.to.shared.u64 t, %1; cvt.u32.u64 %0, t; }" : "=r"(a) : "l"(p));
    return a;
}
__device__ __forceinline__ void mma16816(float* c, const uint32_t* a, const uint32_t* b) {
    asm volatile("mma.sync.aligned.m16n8k16.row.col.f32.bf16.bf16.f32 "
        "{%0,%1,%2,%3}, {%4,%5,%6,%7}, {%8,%9}, {%0,%1,%2,%3};"
        : "+f"(c[0]), "+f"(c[1]), "+f"(c[2]), "+f"(c[3])
        : "r"(a[0]), "r"(a[1]), "r"(a[2]), "r"(a[3]), "r"(b[0]), "r"(b[1]));
}
__device__ __forceinline__ void mma16816f(float* c, const uint32_t* a, const uint32_t* b) {
    asm volatile("mma.sync.aligned.m16n8k16.row.col.f32.f16.f16.f32 "
        "{%0,%1,%2,%3}, {%4,%5,%6,%7}, {%8,%9}, {%0,%1,%2,%3};"
        : "+f"(c[0]), "+f"(c[1]), "+f"(c[2]), "+f"(c[3])
        : "r"(a[0]), "r"(a[1]), "r"(a[2]), "r"(a[3]), "r"(b[0]), "r"(b[1]));
}
#define LDSM_X4(r0,r1,r2,r3,addr) \
    asm volatile("ldmatrix.sync.aligned.m8n8.x4.shared.b16 {%0,%1,%2,%3}, [%4];" \
                 : "=r"(r0),"=r"(r1),"=r"(r2),"=r"(r3) : "r"(addr))
#define LDSM_X4T(r0,r1,r2,r3,addr) \
    asm volatile("ldmatrix.sync.aligned.m8n8.x4.trans.shared.b16 {%0,%1,%2,%3}, [%4];" \
                 : "=r"(r0),"=r"(r1),"=r"(r2),"=r"(r3) : "r"(addr))
#define CVT_BF16X2(res,a,b) asm("cvt.rn.bf16x2.f32 %0, %1, %2;" : "=r"(res) : "f"(b), "f"(a))
#define CVT_F16X2(res,a,b)  asm("cvt.rn.f16x2.f32 %0, %1, %2;" : "=r"(res) : "f"(b), "f"(a))
#define EX2F(y,x) asm("ex2.approx.f32 %0, %1;" : "=f"(y) : "f"(x))
#define CP_ASYNC16(dst, src) \
    asm volatile("cp.async.cg.shared.global [%0], [%1], 16;" :: "r"(dst), "l"(src) : "memory")
#define CP_COMMIT() asm volatile("cp.async.commit_group;" ::: "memory")
#define CP_WAIT(n) asm volatile("cp.async.wait_group %0;" :: "n"(n) : "memory")

__device__ __forceinline__ void split4(const float4 v, uint32_t& h0, uint32_t& h1,
                                       uint32_t& l0, uint32_t& l1) {
    CVT_BF16X2(h0, v.x, v.y);
    CVT_BF16X2(h1, v.z, v.w);
    const float r0 = v.x - __uint_as_float(h0 << 16);
    const float r1 = v.y - __uint_as_float(h0 & 0xffff0000u);
    const float r2 = v.z - __uint_as_float(h1 << 16);
    const float r3 = v.w - __uint_as_float(h1 & 0xffff0000u);
    CVT_BF16X2(l0, r0, r1);
    CVT_BF16X2(l1, r2, r3);
}

// fp16 hi/lo split of a float4
__device__ __forceinline__ void split4_f16(const float4 v, uint32_t& h0, uint32_t& h1,
                                           uint32_t& l0, uint32_t& l1) {
    CVT_F16X2(h0, v.x, v.y);
    CVT_F16X2(h1, v.z, v.w);
    const __half2 hx = *(const __half2*)&h0;
    const __half2 hy = *(const __half2*)&h1;
    const float r0 = v.x - __half2float(__low2half(hx));
    const float r1 = v.y - __half2float(__high2half(hx));
    const float r2 = v.z - __half2float(__low2half(hy));
    const float r3 = v.w - __half2float(__high2half(hy));
    CVT_F16X2(l0, r0, r1);
    CVT_F16X2(l1, r2, r3);
}

// ---------------- merged converts --------------------------------------------
__global__ void __launch_bounds__(256) to_hilo_w(
    const float* __restrict__ w0, const float* __restrict__ w1,
    const float* __restrict__ w2, const float* __restrict__ w3,
    ushort_t* __restrict__ hi, ushort_t* __restrict__ lo)
{
    const int g = blockIdx.y;
    const float* src = g == 0 ? w0 : (g == 1 ? w1 : (g == 2 ? w2 : w3));
    const size_t i = ((size_t)blockIdx.x * 256 + threadIdx.x) * 4;
    const float4 v = *(const float4*)&src[i];
    uint32_t h0, h1, l0, l1;
    split4(v, h0, h1, l0, l1);
    *(uint2*)&hi[g * WSZ + i] = make_uint2(h0, h1);
    *(uint2*)&lo[g * WSZ + i] = make_uint2(l0, l1);
}
__global__ void __launch_bounds__(256) to_hilo_x(
    const float* __restrict__ x0, const float* __restrict__ x1,
    const float* __restrict__ x2,
    ushort_t* __restrict__ hi, ushort_t* __restrict__ lo)
{
    const int g = blockIdx.y;
    const float* src = g == 0 ? x0 : (g == 1 ? x1 : x2);
    const size_t i = ((size_t)blockIdx.x * 256 + threadIdx.x) * 4;
    const float4 v = *(const float4*)&src[i];
    uint32_t h0, h1, l0, l1;
    split4(v, h0, h1, l0, l1);
    *(uint2*)&hi[g * XSZ + i] = make_uint2(h0, h1);
    *(uint2*)&lo[g * XSZ + i] = make_uint2(l0, l1);
}

// ---------------- GEMM body (pure bf16 cp.async path) -------------------------
// mode: 0 = f32 out, 1 = bf16 hi/lo out, 2 = fp16 single out, 3 = fp16 hi/lo out
#define LAH 56
#define LBH 136
#define G_AH 0
#define G_AL 14336
#define G_BH 28672
#define G_BL 37376
#define G_BUF 46080
#define G_BIAS 92160
#define GB_SMEM 92672

__device__ __forceinline__ void gemm_body(
    const ushort_t* __restrict__ Ah, const ushort_t* __restrict__ Al,
    const ushort_t* __restrict__ Bh, const ushort_t* __restrict__ Bl,
    const float* __restrict__ bias, float* __restrict__ Cf,
    ushort_t* __restrict__ Ch, ushort_t* __restrict__ Cl,
    float alpha, int mode)
{
    extern __shared__ char smg[];
    const uint32_t sb = smem_u32(smg);
    const int tid = threadIdx.x, wid = tid >> 5, lane = tid & 31;
    const int n0 = blockIdx.x * 128, m0 = blockIdx.y * 128;
    float* bias_s = (float*)(smg + G_BIAS);
    if (tid < 128) bias_s[tid] = bias[m0 + tid];

    const int wm = wid & 3, wn = wid >> 2;
    float acc[2][8][4];
#pragma unroll
    for (int ms = 0; ms < 2; ms++)
#pragma unroll
        for (int nt = 0; nt < 8; nt++)
#pragma unroll
            for (int i = 0; i < 4; i++) acc[ms][nt][i] = 0.f;

    const int arow = lane & 15, ak8 = (lane >> 4) * 8;
    const int bj = lane >> 3, br = lane & 7;
    const int bk = (bj & 1) * 8 + br, bn8 = (bj >> 1) * 8;

#define G_CP(kt, buf) do {                                                     \
    const uint32_t base = sb + (buf) * G_BUF;                                  \
    _Pragma("unroll")                                                          \
    for (int i = 0; i < 2; i++) {                                              \
        const int id = i * 256 + tid;                                          \
        const int r = id >> 2, c = id & 3;                                     \
        const size_t so = (size_t)(m0 + r) * KDIM + (kt) * 32 + c * 8;         \
        const uint32_t doff = (uint32_t)(r * 112 + c * 16);                    \
        CP_ASYNC16(base + G_AH + doff, Ah + so);                               \
        CP_ASYNC16(base + G_AL + doff, Al + so);                               \
    }                                                                          \
    _Pragma("unroll")                                                          \
    for (int i = 0; i < 2; i++) {                                              \
        const int id = i * 256 + tid;                                          \
        const int r = id >> 4, c = id & 15;                                    \
        const size_t so = (size_t)((kt) * 32 + r) * SEQ + n0 + c * 8;          \
        const uint32_t doff = (uint32_t)(r * 272 + c * 16);                    \
        CP_ASYNC16(base + G_BH + doff, Bh + so);                               \
        CP_ASYNC16(base + G_BL + doff, Bl + so);                               \
    }                                                                          \
} while (0)

    G_CP(0, 0);
    CP_COMMIT();

    const int NKT = KDIM / 32;
    for (int kt = 0; kt < NKT; kt++) {
        __syncthreads();
        if (kt + 1 < NKT) { G_CP(kt + 1, (kt + 1) & 1); CP_COMMIT(); CP_WAIT(1); }
        else CP_WAIT(0);
        __syncthreads();

        const uint32_t base = sb + (kt & 1) * G_BUF;
#pragma unroll
        for (int ks = 0; ks < 2; ks++) {
            uint32_t aF[2][4], aL[2][4];
#pragma unroll
            for (int ms = 0; ms < 2; ms++) {
                const uint32_t ao = (uint32_t)((wm * 32 + ms * 16 + arow) * LAH + ks * 16 + ak8) * 2;
                LDSM_X4(aF[ms][0], aF[ms][1], aF[ms][2], aF[ms][3], base + G_AH + ao);
                LDSM_X4(aL[ms][0], aL[ms][1], aL[ms][2], aL[ms][3], base + G_AL + ao);
            }
#pragma unroll
            for (int nt16 = 0; nt16 < 4; nt16++) {
                uint32_t bH[4], bL[4];
                const uint32_t bo = (uint32_t)((ks * 16 + bk) * LBH + wn * 64 + nt16 * 16 + bn8) * 2;
                LDSM_X4T(bH[0], bH[1], bH[2], bH[3], base + G_BH + bo);
                LDSM_X4T(bL[0], bL[1], bL[2], bL[3], base + G_BL + bo);
#pragma unroll
                for (int ms = 0; ms < 2; ms++)
#pragma unroll
                    for (int s = 0; s < 2; s++) {
                        float* a4 = acc[ms][nt16 * 2 + s];
                        mma16816(a4, aF[ms], &bH[s * 2]);
                        mma16816(a4, aF[ms], &bL[s * 2]);
                        mma16816(a4, aL[ms], &bH[s * 2]);
                    }
            }
        }
    }

    __syncthreads();
    float* Cs = (float*)smg;
    {
        const int rr = lane >> 2, cc = (lane & 3) * 2;
#pragma unroll
        for (int ms = 0; ms < 2; ms++)
#pragma unroll
            for (int nt = 0; nt < 8; nt++) {
                const int r = wm * 32 + ms * 16 + rr;
                const int c = wn * 64 + nt * 8 + cc;
                Cs[r * 132 + c]           = acc[ms][nt][0];
                Cs[r * 132 + c + 1]       = acc[ms][nt][1];
                Cs[(r + 8) * 132 + c]     = acc[ms][nt][2];
                Cs[(r + 8) * 132 + c + 1] = acc[ms][nt][3];
            }
    }
    __syncthreads();
#pragma unroll
    for (int i = 0; i < 16; i++) {
        const int e = i * 256 + tid;
        const int r = e >> 5, c4 = (e & 31) * 4;
        float4 v = *(const float4*)&Cs[r * 132 + c4];
        const float bi = bias_s[r];
        v.x = alpha * (v.x + bi); v.y = alpha * (v.y + bi);
        v.z = alpha * (v.z + bi); v.w = alpha * (v.w + bi);
        const size_t go = (size_t)(m0 + r) * SEQ + n0 + c4;
        if (mode == 0) {
            *(float4*)&Cf[go] = v;
        } else if (mode == 1) {
            uint32_t h0, h1, l0, l1;
            split4(v, h0, h1, l0, l1);
            *(uint2*)&Ch[go] = make_uint2(h0, h1);
            *(uint2*)&Cl[go] = make_uint2(l0, l1);
        } else if (mode == 2) {
            uint32_t f0, f1;
            CVT_F16X2(f0, v.x, v.y);
            CVT_F16X2(f1, v.z, v.w);
            *(uint2*)&Ch[go] = make_uint2(f0, f1);
        } else {
            uint32_t h0, h1, l0, l1;
            split4_f16(v, h0, h1, l0, l1);
            *(uint2*)&Ch[go] = make_uint2(h0, h1);
            *(uint2*)&Cl[go] = make_uint2(l0, l1);
        }
    }
}

__global__ void __launch_bounds__(256, 2) gemm_qkv(
    const ushort_t* __restrict__ wh, const ushort_t* __restrict__ wl,
    const ushort_t* __restrict__ xh, const ushort_t* __restrict__ xl,
    const float* __restrict__ bq, const float* __restrict__ bk,
    const float* __restrict__ bv,
    ushort_t* __restrict__ ph, ushort_t* __restrict__ pl)
{
    const int gi = blockIdx.z >> 1, bb = blockIdx.z & 1;
    const size_t woff = (size_t)gi * WSZ;
    const size_t xoff = (size_t)gi * XSZ + (size_t)bb * ESZ;
    const float* bias = gi == 0 ? bq : (gi == 1 ? bk : bv);
    const float alpha = gi == 0 ? 0.125f * LOG2E : 1.0f;
    const int mode = gi == 0 ? 3 : 2;   // Q -> fp16 hi/lo, K/V -> fp16 single
    gemm_body(wh + woff, wl + woff, xh + xoff, xl + xoff, bias,
              nullptr, ph + xoff, pl + xoff, alpha, mode);
}
__global__ void __launch_bounds__(256, 2) gemm_wo(
    const ushort_t* __restrict__ wh, const ushort_t* __restrict__ wl,
    const ushort_t* __restrict__ ah, const ushort_t* __restrict__ al,
    const float* __restrict__ bo, float* __restrict__ out)
{
    const size_t off = (size_t)blockIdx.z * ESZ;
    gemm_body(wh, wl, ah + off, al + off, bo, out + off, nullptr, nullptr, 1.0f, 0);
}

// ---------------- flash attention: all-fp16, 2 CTAs/SM -----------------------
// QK 2-pass fp16 (Q hi/lo, K single), PV 1-pass fp16. KV double-buffered
// (Kf, Vf), mask single 64-row buffer reloaded per half under the MMAs.
#define PKH 136
#define KVA 17408            // one array (64 x 136 halves)
#define KVB2 34816           // buffer: Kf, Vf
#define MASK_OFF 69632       // 64 x 132 f32 = 33792 B
#define AT_SMEM 103424       // = MASK_OFF + 33792 ; x2 CTAs = 206848 <= 227KB

__global__ void __launch_bounds__(256, 2) attn_mma(
    const ushort_t* __restrict__ Qh, const ushort_t* __restrict__ Ql,
    const ushort_t* __restrict__ Kf, const ushort_t* __restrict__ Vf,
    const float* __restrict__ MASK,
    ushort_t* __restrict__ Oh, ushort_t* __restrict__ Ol)
{
    extern __shared__ char sma[];
    const uint32_t sb = smem_u32(sma);
    const int tid = threadIdx.x, wid = tid >> 5, lane = tid & 31;
    const int b = blockIdx.z, h = blockIdx.y, q0 = blockIdx.x * 128;

    const size_t hoff = ((size_t)b * EMB + h * DH) * SEQ;
    const float* Mg = MASK + (size_t)b * SEQ * SEQ;

#define A_CPKV(k0, buf) do {                                                   \
    const uint32_t base = sb + (buf) * KVB2;                                   \
    _Pragma("unroll")                                                          \
    for (int i = 0; i < 4; i++) {                                              \
        const int id = i * 256 + tid;                                          \
        const int r = id >> 4, c = id & 15;                                    \
        const size_t so = hoff + (size_t)r * SEQ + (k0) + c * 8;               \
        const uint32_t doff = (uint32_t)(r * 272 + c * 16);                    \
        CP_ASYNC16(base +       doff, Kf + so);                                \
        CP_ASYNC16(base + KVA + doff, Vf + so);                                \
    }                                                                          \
} while (0)

// loads 64 mask rows starting at key row k0
#define A_CPMASK(k0) do {                                                      \
    const uint32_t mb = sb + MASK_OFF;                                         \
    _Pragma("unroll")                                                          \
    for (int i = 0; i < 8; i++) {                                              \
        const int id = i * 256 + tid;                                          \
        const int r = id >> 5, c32 = id & 31;                                  \
        CP_ASYNC16(mb + (uint32_t)(r * 132 + c32 * 4) * 4,                     \
                   Mg + (size_t)((k0) + r) * SEQ + q0 + c32 * 4);              \
    }                                                                          \
} while (0)

    // ---- preamble: Q (into KV buf1) + mask(0,h0) (group A); KV0 (group B) ----
    {
        const uint32_t qb = sb + KVB2;
#pragma unroll
        for (int i = 0; i < 4; i++) {
            const int id = i * 256 + tid;
            const int r = id >> 4, c = id & 15;
            const size_t so = hoff + (size_t)r * SEQ + q0 + c * 8;
            const uint32_t doff = (uint32_t)(r * 272 + c * 16);
            CP_ASYNC16(qb + doff, Qh + so);
            CP_ASYNC16(qb + KVA + doff, Ql + so);
        }
    }
    A_CPMASK(0);
    CP_COMMIT();
    A_CPKV(0, 0);
    CP_COMMIT();
    CP_WAIT(1);          // Q + mask(0,h0) arrived
    __syncthreads();

    const int arow_k = (lane & 7) + ((lane >> 4) << 3);
    const int amcol  = ((lane >> 3) & 1) * 8;
    uint32_t qfh[4][4], qfl[4][4];
#pragma unroll
    for (int ks = 0; ks < 4; ks++) {
        const uint32_t ao = (uint32_t)((ks * 16 + arow_k) * PKH + wid * 16 + amcol) * 2;
        LDSM_X4T(qfh[ks][0], qfh[ks][1], qfh[ks][2], qfh[ks][3], sb + KVB2 + ao);
        LDSM_X4T(qfl[ks][0], qfl[ks][1], qfl[ks][2], qfl[ks][3], sb + KVB2 + KVA + ao);
    }
    __syncthreads();   // Q region free for KV buf1 (cp issued in tile 0)

    const int bj = lane >> 3, br = lane & 7;
    const int bk = (bj & 1) * 8 + br, bn8 = (bj >> 1) * 8;      // trans (K)
    const int bvrow = ((lane >> 4) & 1) * 8 + br;               // plain (V)
    const int bvk8  = ((lane >> 3) & 1) * 8;

    float o[8][4];
#pragma unroll
    for (int d = 0; d < 8; d++)
#pragma unroll
        for (int j = 0; j < 4; j++) o[d][j] = 0.f;
    float lsum0 = 0.f, lsum1 = 0.f;

    const int qr = wid * 16 + (lane >> 2);
    const int krow2 = 2 * (lane & 3);
    const float* Ms = (const float*)(sma + MASK_OFF);

    const int NT = SEQ / 128;
    for (int kt = 0; kt < NT; kt++) {
        CP_WAIT(0);
        __syncthreads();   // KV kt + mask(kt,h0) resident; prior buf reads done

        const uint32_t kvb = sb + (kt & 1) * KVB2;

#pragma unroll
        for (int h2 = 0; h2 < 2; h2++) {
            if (h2 == 1) {          // mask(kt,h1) must have arrived
                CP_WAIT(0);
                __syncthreads();
            }
            // ---- mask (this half) -> accumulator init ----
            float s[8][4];
#pragma unroll
            for (int nt = 0; nt < 8; nt++) {
                const float* mp = Ms + (nt * 8 + krow2) * 132 + qr;
                s[nt][0] = mp[0]   * LOG2E;
                s[nt][1] = mp[132] * LOG2E;
                s[nt][2] = mp[8]   * LOG2E;
                s[nt][3] = mp[140] * LOG2E;
            }
            __syncthreads();        // all warps consumed the mask buffer
            if (h2 == 0) {
                A_CPMASK(kt * 128 + 64);
                CP_COMMIT();
            } else if (kt + 1 < NT) {
                A_CPKV((kt + 1) * 128, (kt + 1) & 1);
                A_CPMASK((kt + 1) * 128);
                CP_COMMIT();
            }
            // ---- QK mma (2-pass fp16), 64 keys ----
#pragma unroll
            for (int ks = 0; ks < 4; ks++)
#pragma unroll
                for (int np = 0; np < 4; np++) {
                    uint32_t kf[4];
                    const uint32_t bo = (uint32_t)((ks * 16 + bk) * PKH
                                                   + h2 * 64 + np * 16 + bn8) * 2;
                    LDSM_X4T(kf[0], kf[1], kf[2], kf[3], kvb + bo);
#pragma unroll
                    for (int s2 = 0; s2 < 2; s2++) {
                        float* a4 = s[np * 2 + s2];
                        mma16816f(a4, qfh[ks], &kf[s2 * 2]);
                        mma16816f(a4, qfl[ks], &kf[s2 * 2]);
                    }
                }
            // ---- exp2 + row sums ----
            float rs0 = 0.f, rs1 = 0.f;
#pragma unroll
            for (int nt = 0; nt < 8; nt++) {
#pragma unroll
                for (int j = 0; j < 4; j++) EX2F(s[nt][j], s[nt][j]);
                rs0 += s[nt][0] + s[nt][1];
                rs1 += s[nt][2] + s[nt][3];
            }
            rs0 += __shfl_xor_sync(0xffffffffu, rs0, 1);
            rs0 += __shfl_xor_sync(0xffffffffu, rs0, 2);
            rs1 += __shfl_xor_sync(0xffffffffu, rs1, 1);
            rs1 += __shfl_xor_sync(0xffffffffu, rs1, 2);
            lsum0 += rs0;
            lsum1 += rs1;

            // ---- pack P as fp16 (single) ----
            uint32_t pa[4][4];
#pragma unroll
            for (int ks = 0; ks < 4; ks++) {
                const float* u = s[ks * 2];
                const float* w = s[ks * 2 + 1];
                CVT_F16X2(pa[ks][0], u[0], u[1]);
                CVT_F16X2(pa[ks][1], u[2], u[3]);
                CVT_F16X2(pa[ks][2], w[0], w[1]);
                CVT_F16X2(pa[ks][3], w[2], w[3]);
            }
            // ---- PV mma (1-pass fp16): O += P @ V ----
#pragma unroll
            for (int ks = 0; ks < 4; ks++)
#pragma unroll
                for (int dp = 0; dp < 4; dp++) {
                    uint32_t vf[4];
                    const uint32_t bo = (uint32_t)((dp * 16 + bvrow) * PKH
                                                   + h2 * 64 + ks * 16 + bvk8) * 2;
                    LDSM_X4(vf[0], vf[1], vf[2], vf[3], kvb + KVA + bo);
#pragma unroll
                    for (int s2 = 0; s2 < 2; s2++)
                        mma16816f(o[dp * 2 + s2], pa[ks], &vf[s2 * 2]);
                }
        }
    }

    // ---- normalize, transpose via smem, hi/lo coalesced store ----
    const float inv0 = 1.f / lsum0, inv1 = 1.f / lsum1;
    __syncthreads();
    float* Os = (float*)sma;   // [64 dh][132] — aliases KV bufs (dead)
#pragma unroll
    for (int d = 0; d < 8; d++) {
        const int dc = d * 8 + krow2;
        Os[dc * 132 + qr]           = o[d][0] * inv0;
        Os[(dc + 1) * 132 + qr]     = o[d][1] * inv0;
        Os[dc * 132 + qr + 8]       = o[d][2] * inv1;
        Os[(dc + 1) * 132 + qr + 8] = o[d][3] * inv1;
    }
    __syncthreads();
#pragma unroll
    for (int i = 0; i < 8; i++) {
        const int e = i * 256 + tid;
        const int r = e >> 5, c4 = (e & 31) * 4;
        const float4 v = *(const float4*)&Os[r * 132 + c4];
        uint32_t h0, h1, l0, l1;
        split4(v, h0, h1, l0, l1);
        const size_t go = hoff + (size_t)r * SEQ + q0 + c4;
        *(uint2*)&Oh[go] = make_uint2(h0, h1);
        *(uint2*)&Ol[go] = make_uint2(l0, l1);
    }
}

// ---------------------------------------------------------------------------
extern "C" void kernel_launch(void* const* d_in, const int* in_sizes, int n_in,
                              void* d_out, int out_size)
{
    const float* q   = (const float*)d_in[0];
    const float* k   = (const float*)d_in[1];
    const float* v   = (const float*)d_in[2];
    const float* msk = (const float*)d_in[3];
    const float* Wq  = (const float*)d_in[4];
    const float* bq  = (const float*)d_in[5];
    const float* Wk  = (const float*)d_in[6];
    const float* bk  = (const float*)d_in[7];
    const float* Wv  = (const float*)d_in[8];
    const float* bv  = (const float*)d_in[9];
    const float* Wo  = (const float*)d_in[10];
    const float* bo  = (const float*)d_in[11];
    float* out = (float*)d_out;

    void *pwh, *pwl, *pxh, *pxl, *pph, *ppl, *path, *patl;
    cudaGetSymbolAddress(&pwh, g_wh);
    cudaGetSymbolAddress(&pwl, g_wl);
    cudaGetSymbolAddress(&pxh, g_xh);
    cudaGetSymbolAddress(&pxl, g_xl);
    cudaGetSymbolAddress(&pph, g_ph);
    cudaGetSymbolAddress(&ppl, g_pl);
    cudaGetSymbolAddress(&path, g_ath);
    cudaGetSymbolAddress(&patl, g_atl);

    ushort_t* wh = (ushort_t*)pwh;  ushort_t* wl = (ushort_t*)pwl;
    ushort_t* xh = (ushort_t*)pxh;  ushort_t* xl = (ushort_t*)pxl;
    ushort_t* ph = (ushort_t*)pph;  ushort_t* pl = (ushort_t*)ppl;
    ushort_t* ath = (ushort_t*)path; ushort_t* atl = (ushort_t*)patl;

    cudaFuncSetAttribute(gemm_qkv, cudaFuncAttributeMaxDynamicSharedMemorySize, GB_SMEM);
    cudaFuncSetAttribute(gemm_wo,  cudaFuncAttributeMaxDynamicSharedMemorySize, GB_SMEM);
    cudaFuncSetAttribute(attn_mma, cudaFuncAttributeMaxDynamicSharedMemorySize, AT_SMEM);

    // 1. converts
    to_hilo_w<<<dim3((unsigned)(WSZ / 1024), 4), 256>>>(Wq, Wk, Wv, Wo, wh, wl);
    to_hilo_x<<<dim3((unsigned)(XSZ / 1024), 3), 256>>>(q, k, v, xh, xl);

    // 2. merged QKV projections (Q -> fp16 hi/lo, K/V -> fp16 single)
    dim3 gq(SEQ / 128, EMB / 128, 6);
    gemm_qkv<<<gq, 256, GB_SMEM>>>(wh, wl, xh, xl, bq, bk, bv, ph, pl);

    // 3. attention (2 CTAs/SM)
    dim3 ga(SEQ / 128, NH, BATCH);
    attn_mma<<<ga, 256, AT_SMEM>>>(ph + 0 * XSZ, pl + 0 * XSZ,
                                   ph + 1 * XSZ, ph + 2 * XSZ,
                                   msk, ath, atl);

    // 4. output projection
    dim3 go(SEQ / 128, EMB / 128, BATCH);
    gemm_wo<<<go, 256, GB_SMEM>>>(wh + 3 * WSZ, wl + 3 * WSZ, ath, atl, bo, out);
}

// round 14
// speedup vs baseline: 1.0118x; 1.0118x over previous
#include <cuda_runtime.h>
#include <cuda_fp16.h>
#include <cstdint>

#define BATCH 2
#define EMB   1024
#define SEQ   2048
#define NH    16
#define DH    64
#define KDIM  1024
#define LOG2E 1.4426950408889634f
typedef unsigned short ushort_t;

#define WSZ ((size_t)KDIM * EMB)
#define XSZ ((size_t)BATCH * EMB * SEQ)
#define ESZ ((size_t)EMB * SEQ)

// ---------------- scratch ----------------------------------------------------
__device__ ushort_t g_wh[4 * WSZ];
__device__ ushort_t g_wl[4 * WSZ];
__device__ ushort_t g_xh[3 * XSZ];
__device__ ushort_t g_xl[3 * XSZ];
__device__ ushort_t g_ph[3 * XSZ];   // Q fp16-hi, K fp16, V fp16
__device__ ushort_t g_pl[3 * XSZ];   // Q fp16-lo, (unused), (unused)
__device__ ushort_t g_ath[XSZ];
__device__ ushort_t g_atl[XSZ];

// ---------------- helpers ----------------------------------------------------
__device__ __forceinline__ uint32_t smem_u32(const void* p) {
    uint32_t a;
    asm("{ .reg .u64 t; cvta.to.shared.u64 t, %1; cvt.u32.u64 %0, t; }" : "=r"(a) : "l"(p));
    return a;
}
__device__ __forceinline__ void mma16816(float* c, const uint32_t* a, const uint32_t* b) {
    asm volatile("mma.sync.aligned.m16n8k16.row.col.f32.bf16.bf16.f32 "
        "{%0,%1,%2,%3}, {%4,%5,%6,%7}, {%8,%9}, {%0,%1,%2,%3};"
        : "+f"(c[0]), "+f"(c[1]), "+f"(c[2]), "+f"(c[3])
        : "r"(a[0]), "r"(a[1]), "r"(a[2]), "r"(a[3]), "r"(b[0]), "r"(b[1]));
}
__device__ __forceinline__ void mma16816f(float* c, const uint32_t* a, const uint32_t* b) {
    asm volatile("mma.sync.aligned.m16n8k16.row.col.f32.f16.f16.f32 "
        "{%0,%1,%2,%3}, {%4,%5,%6,%7}, {%8,%9}, {%0,%1,%2,%3};"
        : "+f"(c[0]), "+f"(c[1]), "+f"(c[2]), "+f"(c[3])
        : "r"(a[0]), "r"(a[1]), "r"(a[2]), "r"(a[3]), "r"(b[0]), "r"(b[1]));
}
#define LDSM_X4(r0,r1,r2,r3,addr) \
    asm volatile("ldmatrix.sync.aligned.m8n8.x4.shared.b16 {%0,%1,%2,%3}, [%4];" \
                 : "=r"(r0),"=r"(r1),"=r"(r2),"=r"(r3) : "r"(addr))
#define LDSM_X4T(r0,r1,r2,r3,addr) \
    asm volatile("ldmatrix.sync.aligned.m8n8.x4.trans.shared.b16 {%0,%1,%2,%3}, [%4];" \
                 : "=r"(r0),"=r"(r1),"=r"(r2),"=r"(r3) : "r"(addr))
#define CVT_BF16X2(res,a,b) asm("cvt.rn.bf16x2.f32 %0, %1, %2;" : "=r"(res) : "f"(b), "f"(a))
#define CVT_F16X2(res,a,b)  asm("cvt.rn.f16x2.f32 %0, %1, %2;" : "=r"(res) : "f"(b), "f"(a))
#define EX2F(y,x) asm("ex2.approx.f32 %0, %1;" : "=f"(y) : "f"(x))
#define CP_ASYNC16(dst, src) \
    asm volatile("cp.async.cg.shared.global [%0], [%1], 16;" :: "r"(dst), "l"(src) : "memory")
#define CP_COMMIT() asm volatile("cp.async.commit_group;" ::: "memory")
#define CP_WAIT(n) asm volatile("cp.async.wait_group %0;" :: "n"(n) : "memory")

__device__ __forceinline__ void split4(const float4 v, uint32_t& h0, uint32_t& h1,
                                       uint32_t& l0, uint32_t& l1) {
    CVT_BF16X2(h0, v.x, v.y);
    CVT_BF16X2(h1, v.z, v.w);
    const float r0 = v.x - __uint_as_float(h0 << 16);
    const float r1 = v.y - __uint_as_float(h0 & 0xffff0000u);
    const float r2 = v.z - __uint_as_float(h1 << 16);
    const float r3 = v.w - __uint_as_float(h1 & 0xffff0000u);
    CVT_BF16X2(l0, r0, r1);
    CVT_BF16X2(l1, r2, r3);
}

// fp16 hi/lo split of a float4
__device__ __forceinline__ void split4_f16(const float4 v, uint32_t& h0, uint32_t& h1,
                                           uint32_t& l0, uint32_t& l1) {
    CVT_F16X2(h0, v.x, v.y);
    CVT_F16X2(h1, v.z, v.w);
    const __half2 hx = *(const __half2*)&h0;
    const __half2 hy = *(const __half2*)&h1;
    const float r0 = v.x - __half2float(__low2half(hx));
    const float r1 = v.y - __half2float(__high2half(hx));
    const float r2 = v.z - __half2float(__low2half(hy));
    const float r3 = v.w - __half2float(__high2half(hy));
    CVT_F16X2(l0, r0, r1);
    CVT_F16X2(l1, r2, r3);
}

// ---------------- merged converts --------------------------------------------
__global__ void __launch_bounds__(256) to_hilo_w(
    const float* __restrict__ w0, const float* __restrict__ w1,
    const float* __restrict__ w2, const float* __restrict__ w3,
    ushort_t* __restrict__ hi, ushort_t* __restrict__ lo)
{
    const int g = blockIdx.y;
    const float* src = g == 0 ? w0 : (g == 1 ? w1 : (g == 2 ? w2 : w3));
    const size_t i = ((size_t)blockIdx.x * 256 + threadIdx.x) * 4;
    const float4 v = *(const float4*)&src[i];
    uint32_t h0, h1, l0, l1;
    split4(v, h0, h1, l0, l1);
    *(uint2*)&hi[g * WSZ + i] = make_uint2(h0, h1);
    *(uint2*)&lo[g * WSZ + i] = make_uint2(l0, l1);
}
__global__ void __launch_bounds__(256) to_hilo_x(
    const float* __restrict__ x0, const float* __restrict__ x1,
    const float* __restrict__ x2,
    ushort_t* __restrict__ hi, ushort_t* __restrict__ lo)
{
    const int g = blockIdx.y;
    const float* src = g == 0 ? x0 : (g == 1 ? x1 : x2);
    const size_t i = ((size_t)blockIdx.x * 256 + threadIdx.x) * 4;
    const float4 v = *(const float4*)&src[i];
    uint32_t h0, h1, l0, l1;
    split4(v, h0, h1, l0, l1);
    *(uint2*)&hi[g * XSZ + i] = make_uint2(h0, h1);
    *(uint2*)&lo[g * XSZ + i] = make_uint2(l0, l1);
}

// ---------------- GEMM body (pure bf16 cp.async path) -------------------------
// mode: 0 = f32 out, 1 = bf16 hi/lo out, 2 = fp16 single out, 3 = fp16 hi/lo out
#define LAH 56
#define LBH 136
#define G_AH 0
#define G_AL 14336
#define G_BH 28672
#define G_BL 37376
#define G_BUF 46080
#define G_BIAS 92160
#define GB_SMEM 92672

__device__ __forceinline__ void gemm_body(
    const ushort_t* __restrict__ Ah, const ushort_t* __restrict__ Al,
    const ushort_t* __restrict__ Bh, const ushort_t* __restrict__ Bl,
    const float* __restrict__ bias, float* __restrict__ Cf,
    ushort_t* __restrict__ Ch, ushort_t* __restrict__ Cl,
    float alpha, int mode)
{
    extern __shared__ char smg[];
    const uint32_t sb = smem_u32(smg);
    const int tid = threadIdx.x, wid = tid >> 5, lane = tid & 31;
    const int n0 = blockIdx.x * 128, m0 = blockIdx.y * 128;
    float* bias_s = (float*)(smg + G_BIAS);
    if (tid < 128) bias_s[tid] = bias[m0 + tid];

    const int wm = wid & 3, wn = wid >> 2;
    float acc[2][8][4];
#pragma unroll
    for (int ms = 0; ms < 2; ms++)
#pragma unroll
        for (int nt = 0; nt < 8; nt++)
#pragma unroll
            for (int i = 0; i < 4; i++) acc[ms][nt][i] = 0.f;

    const int arow = lane & 15, ak8 = (lane >> 4) * 8;
    const int bj = lane >> 3, br = lane & 7;
    const int bk = (bj & 1) * 8 + br, bn8 = (bj >> 1) * 8;

#define G_CP(kt, buf) do {                                                     \
    const uint32_t base = sb + (buf) * G_BUF;                                  \
    _Pragma("unroll")                                                          \
    for (int i = 0; i < 2; i++) {                                              \
        const int id = i * 256 + tid;                                          \
        const int r = id >> 2, c = id & 3;                                     \
        const size_t so = (size_t)(m0 + r) * KDIM + (kt) * 32 + c * 8;         \
        const uint32_t doff = (uint32_t)(r * 112 + c * 16);                    \
        CP_ASYNC16(base + G_AH + doff, Ah + so);                               \
        CP_ASYNC16(base + G_AL + doff, Al + so);                               \
    }                                                                          \
    _Pragma("unroll")                                                          \
    for (int i = 0; i < 2; i++) {                                              \
        const int id = i * 256 + tid;                                          \
        const int r = id >> 4, c = id & 15;                                    \
        const size_t so = (size_t)((kt) * 32 + r) * SEQ + n0 + c * 8;          \
        const uint32_t doff = (uint32_t)(r * 272 + c * 16);                    \
        CP_ASYNC16(base + G_BH + doff, Bh + so);                               \
        CP_ASYNC16(base + G_BL + doff, Bl + so);                               \
    }                                                                          \
} while (0)

    G_CP(0, 0);
    CP_COMMIT();

    const int NKT = KDIM / 32;
    for (int kt = 0; kt < NKT; kt++) {
        __syncthreads();
        if (kt + 1 < NKT) { G_CP(kt + 1, (kt + 1) & 1); CP_COMMIT(); CP_WAIT(1); }
        else CP_WAIT(0);
        __syncthreads();

        const uint32_t base = sb + (kt & 1) * G_BUF;
#pragma unroll
        for (int ks = 0; ks < 2; ks++) {
            uint32_t aF[2][4], aL[2][4];
#pragma unroll
            for (int ms = 0; ms < 2; ms++) {
                const uint32_t ao = (uint32_t)((wm * 32 + ms * 16 + arow) * LAH + ks * 16 + ak8) * 2;
                LDSM_X4(aF[ms][0], aF[ms][1], aF[ms][2], aF[ms][3], base + G_AH + ao);
                LDSM_X4(aL[ms][0], aL[ms][1], aL[ms][2], aL[ms][3], base + G_AL + ao);
            }
#pragma unroll
            for (int nt16 = 0; nt16 < 4; nt16++) {
                uint32_t bH[4], bL[4];
                const uint32_t bo = (uint32_t)((ks * 16 + bk) * LBH + wn * 64 + nt16 * 16 + bn8) * 2;
                LDSM_X4T(bH[0], bH[1], bH[2], bH[3], base + G_BH + bo);
                LDSM_X4T(bL[0], bL[1], bL[2], bL[3], base + G_BL + bo);
#pragma unroll
                for (int ms = 0; ms < 2; ms++)
#pragma unroll
                    for (int s = 0; s < 2; s++) {
                        float* a4 = acc[ms][nt16 * 2 + s];
                        mma16816(a4, aF[ms], &bH[s * 2]);
                        mma16816(a4, aF[ms], &bL[s * 2]);
                        mma16816(a4, aL[ms], &bH[s * 2]);
                    }
            }
        }
    }

    __syncthreads();
    float* Cs = (float*)smg;
    {
        const int rr = lane >> 2, cc = (lane & 3) * 2;
#pragma unroll
        for (int ms = 0; ms < 2; ms++)
#pragma unroll
            for (int nt = 0; nt < 8; nt++) {
                const int r = wm * 32 + ms * 16 + rr;
                const int c = wn * 64 + nt * 8 + cc;
                Cs[r * 132 + c]           = acc[ms][nt][0];
                Cs[r * 132 + c + 1]       = acc[ms][nt][1];
                Cs[(r + 8) * 132 + c]     = acc[ms][nt][2];
                Cs[(r + 8) * 132 + c + 1] = acc[ms][nt][3];
            }
    }
    __syncthreads();
#pragma unroll
    for (int i = 0; i < 16; i++) {
        const int e = i * 256 + tid;
        const int r = e >> 5, c4 = (e & 31) * 4;
        float4 v = *(const float4*)&Cs[r * 132 + c4];
        const float bi = bias_s[r];
        v.x = alpha * (v.x + bi); v.y = alpha * (v.y + bi);
        v.z = alpha * (v.z + bi); v.w = alpha * (v.w + bi);
        const size_t go = (size_t)(m0 + r) * SEQ + n0 + c4;
        if (mode == 0) {
            *(float4*)&Cf[go] = v;
        } else if (mode == 1) {
            uint32_t h0, h1, l0, l1;
            split4(v, h0, h1, l0, l1);
            *(uint2*)&Ch[go] = make_uint2(h0, h1);
            *(uint2*)&Cl[go] = make_uint2(l0, l1);
        } else if (mode == 2) {
            uint32_t f0, f1;
            CVT_F16X2(f0, v.x, v.y);
            CVT_F16X2(f1, v.z, v.w);
            *(uint2*)&Ch[go] = make_uint2(f0, f1);
        } else {
            uint32_t h0, h1, l0, l1;
            split4_f16(v, h0, h1, l0, l1);
            *(uint2*)&Ch[go] = make_uint2(h0, h1);
            *(uint2*)&Cl[go] = make_uint2(l0, l1);
        }
    }
}

__global__ void __launch_bounds__(256, 2) gemm_qkv(
    const ushort_t* __restrict__ wh, const ushort_t* __restrict__ wl,
    const ushort_t* __restrict__ xh, const ushort_t* __restrict__ xl,
    const float* __restrict__ bq, const float* __restrict__ bk,
    const float* __restrict__ bv,
    ushort_t* __restrict__ ph, ushort_t* __restrict__ pl)
{
    const int gi = blockIdx.z >> 1, bb = blockIdx.z & 1;
    const size_t woff = (size_t)gi * WSZ;
    const size_t xoff = (size_t)gi * XSZ + (size_t)bb * ESZ;
    const float* bias = gi == 0 ? bq : (gi == 1 ? bk : bv);
    const float alpha = gi == 0 ? 0.125f * LOG2E : 1.0f;
    const int mode = gi == 0 ? 3 : 2;   // Q -> fp16 hi/lo, K/V -> fp16 single
    gemm_body(wh + woff, wl + woff, xh + xoff, xl + xoff, bias,
              nullptr, ph + xoff, pl + xoff, alpha, mode);
}
__global__ void __launch_bounds__(256, 2) gemm_wo(
    const ushort_t* __restrict__ wh, const ushort_t* __restrict__ wl,
    const ushort_t* __restrict__ ah, const ushort_t* __restrict__ al,
    const float* __restrict__ bo, float* __restrict__ out)
{
    const size_t off = (size_t)blockIdx.z * ESZ;
    gemm_body(wh, wl, ah + off, al + off, bo, out + off, nullptr, nullptr, 1.0f, 0);
}

// ---------------- flash attention: all-fp16, wide scheduling window ----------
// QK 2-pass fp16 (Q hi/lo, K single), PV 1-pass fp16. 128-key tile: BOTH
// halves' QK scores computed first (s[16][4]), then exp/pack/PV per half in
// one basic block so PV(h0) MMAs overlap exp(h1) MUFU work. 1 CTA/SM,
// 128-row mask single buffer (R12 base).
#define PKH 136
#define KVA 17408            // one array (64 x 136 halves)
#define KVB2 34816           // buffer: Kf, Vf
#define MASK_OFF 69632       // 128 x 132 f32 = 67584 B
#define AT_SMEM 137216       // = MASK_OFF + 67584

__global__ void __launch_bounds__(256) attn_mma(
    const ushort_t* __restrict__ Qh, const ushort_t* __restrict__ Ql,
    const ushort_t* __restrict__ Kf, const ushort_t* __restrict__ Vf,
    const float* __restrict__ MASK,
    ushort_t* __restrict__ Oh, ushort_t* __restrict__ Ol)
{
    extern __shared__ char sma[];
    const uint32_t sb = smem_u32(sma);
    const int tid = threadIdx.x, wid = tid >> 5, lane = tid & 31;
    const int b = blockIdx.z, h = blockIdx.y, q0 = blockIdx.x * 128;

    const size_t hoff = ((size_t)b * EMB + h * DH) * SEQ;
    const float* Mg = MASK + (size_t)b * SEQ * SEQ;

#define A_CPKV(k0, buf) do {                                                   \
    const uint32_t base = sb + (buf) * KVB2;                                   \
    _Pragma("unroll")                                                          \
    for (int i = 0; i < 4; i++) {                                              \
        const int id = i * 256 + tid;                                          \
        const int r = id >> 4, c = id & 15;                                    \
        const size_t so = hoff + (size_t)r * SEQ + (k0) + c * 8;               \
        const uint32_t doff = (uint32_t)(r * 272 + c * 16);                    \
        CP_ASYNC16(base +       doff, Kf + so);                                \
        CP_ASYNC16(base + KVA + doff, Vf + so);                                \
    }                                                                          \
} while (0)

// loads 128 mask rows starting at key row k0
#define A_CPMASK(k0) do {                                                      \
    const uint32_t mb = sb + MASK_OFF;                                         \
    _Pragma("unroll")                                                          \
    for (int i = 0; i < 16; i++) {                                             \
        const int id = i * 256 + tid;                                          \
        const int r = id >> 5, c32 = id & 31;                                  \
        CP_ASYNC16(mb + (uint32_t)(r * 132 + c32 * 4) * 4,                     \
                   Mg + (size_t)((k0) + r) * SEQ + q0 + c32 * 4);              \
    }                                                                          \
} while (0)

    // ---- preamble: Q (into KV buf1) + mask0 (group A); KV0 (group B) ----
    {
        const uint32_t qb = sb + KVB2;
#pragma unroll
        for (int i = 0; i < 4; i++) {
            const int id = i * 256 + tid;
            const int r = id >> 4, c = id & 15;
            const size_t so = hoff + (size_t)r * SEQ + q0 + c * 8;
            const uint32_t doff = (uint32_t)(r * 272 + c * 16);
            CP_ASYNC16(qb + doff, Qh + so);
            CP_ASYNC16(qb + KVA + doff, Ql + so);
        }
    }
    A_CPMASK(0);
    CP_COMMIT();
    A_CPKV(0, 0);
    CP_COMMIT();
    CP_WAIT(1);          // Q + mask0 arrived
    __syncthreads();

    const int arow_k = (lane & 7) + ((lane >> 4) << 3);
    const int amcol  = ((lane >> 3) & 1) * 8;
    uint32_t qfh[4][4], qfl[4][4];
#pragma unroll
    for (int ks = 0; ks < 4; ks++) {
        const uint32_t ao = (uint32_t)((ks * 16 + arow_k) * PKH + wid * 16 + amcol) * 2;
        LDSM_X4T(qfh[ks][0], qfh[ks][1], qfh[ks][2], qfh[ks][3], sb + KVB2 + ao);
        LDSM_X4T(qfl[ks][0], qfl[ks][1], qfl[ks][2], qfl[ks][3], sb + KVB2 + KVA + ao);
    }
    __syncthreads();   // Q region free for KV buf1 (cp issued in tile 0)

    const int bj = lane >> 3, br = lane & 7;
    const int bk = (bj & 1) * 8 + br, bn8 = (bj >> 1) * 8;      // trans (K)
    const int bvrow = ((lane >> 4) & 1) * 8 + br;               // plain (V)
    const int bvk8  = ((lane >> 3) & 1) * 8;

    float o[8][4];
#pragma unroll
    for (int d = 0; d < 8; d++)
#pragma unroll
        for (int j = 0; j < 4; j++) o[d][j] = 0.f;
    float lsum0 = 0.f, lsum1 = 0.f;

    const int qr = wid * 16 + (lane >> 2);
    const int krow2 = 2 * (lane & 3);
    const float* Ms = (const float*)(sma + MASK_OFF);

    const int NT = SEQ / 128;
    for (int kt = 0; kt < NT; kt++) {
        CP_WAIT(0);
        __syncthreads();   // KV kt + mask kt resident; prior buf reads done

        const uint32_t kvb = sb + (kt & 1) * KVB2;

        // ---- mask (both halves) -> accumulator init ----
        float s[16][4];
#pragma unroll
        for (int nt = 0; nt < 16; nt++) {
            const float* mp = Ms + (nt * 8 + krow2) * 132 + qr;
            s[nt][0] = mp[0]   * LOG2E;
            s[nt][1] = mp[132] * LOG2E;
            s[nt][2] = mp[8]   * LOG2E;
            s[nt][3] = mp[140] * LOG2E;
        }
        __syncthreads();   // all warps consumed the mask buffer

        if (kt + 1 < NT) {
            A_CPKV((kt + 1) * 128, (kt + 1) & 1);
            A_CPMASK((kt + 1) * 128);
            CP_COMMIT();
        }

        // ---- QK mma (2-pass fp16), BOTH halves (128 keys) ----
#pragma unroll
        for (int h2 = 0; h2 < 2; h2++)
#pragma unroll
            for (int ks = 0; ks < 4; ks++)
#pragma unroll
                for (int np = 0; np < 4; np++) {
                    uint32_t kf[4];
                    const uint32_t bo = (uint32_t)((ks * 16 + bk) * PKH
                                                   + h2 * 64 + np * 16 + bn8) * 2;
                    LDSM_X4T(kf[0], kf[1], kf[2], kf[3], kvb + bo);
#pragma unroll
                    for (int s2 = 0; s2 < 2; s2++) {
                        float* a4 = s[h2 * 8 + np * 2 + s2];
                        mma16816f(a4, qfh[ks], &kf[s2 * 2]);
                        mma16816f(a4, qfl[ks], &kf[s2 * 2]);
                    }
                }

        // ---- per half: exp/sums, pack, PV — one basic block so PV(h0)
        //      MMAs overlap exp(h1) MUFU work in the issue schedule ----
#pragma unroll
        for (int h2 = 0; h2 < 2; h2++) {
            float* sh = &s[h2 * 8][0];
            float rs0 = 0.f, rs1 = 0.f;
#pragma unroll
            for (int nt = 0; nt < 8; nt++) {
                float* sn = sh + nt * 4;
#pragma unroll
                for (int j = 0; j < 4; j++) EX2F(sn[j], sn[j]);
                rs0 += sn[0] + sn[1];
                rs1 += sn[2] + sn[3];
            }
            rs0 += __shfl_xor_sync(0xffffffffu, rs0, 1);
            rs0 += __shfl_xor_sync(0xffffffffu, rs0, 2);
            rs1 += __shfl_xor_sync(0xffffffffu, rs1, 1);
            rs1 += __shfl_xor_sync(0xffffffffu, rs1, 2);
            lsum0 += rs0;
            lsum1 += rs1;

            uint32_t pa[4][4];
#pragma unroll
            for (int ks = 0; ks < 4; ks++) {
                const float* u = sh + ks * 8;
                const float* w = sh + ks * 8 + 4;
                CVT_F16X2(pa[ks][0], u[0], u[1]);
                CVT_F16X2(pa[ks][1], u[2], u[3]);
                CVT_F16X2(pa[ks][2], w[0], w[1]);
                CVT_F16X2(pa[ks][3], w[2], w[3]);
            }
#pragma unroll
            for (int ks = 0; ks < 4; ks++)
#pragma unroll
                for (int dp = 0; dp < 4; dp++) {
                    uint32_t vf[4];
                    const uint32_t bo = (uint32_t)((dp * 16 + bvrow) * PKH
                                                   + h2 * 64 + ks * 16 + bvk8) * 2;
                    LDSM_X4(vf[0], vf[1], vf[2], vf[3], kvb + KVA + bo);
#pragma unroll
                    for (int s2 = 0; s2 < 2; s2++)
                        mma16816f(o[dp * 2 + s2], pa[ks], &vf[s2 * 2]);
                }
        }
    }

    // ---- normalize, transpose via smem, hi/lo coalesced store ----
    const float inv0 = 1.f / lsum0, inv1 = 1.f / lsum1;
    __syncthreads();
    float* Os = (float*)sma;   // [64 dh][132] — aliases KV bufs (dead)
#pragma unroll
    for (int d = 0; d < 8; d++) {
        const int dc = d * 8 + krow2;
        Os[dc * 132 + qr]           = o[d][0] * inv0;
        Os[(dc + 1) * 132 + qr]     = o[d][1] * inv0;
        Os[dc * 132 + qr + 8]       = o[d][2] * inv1;
        Os[(dc + 1) * 132 + qr + 8] = o[d][3] * inv1;
    }
    __syncthreads();
#pragma unroll
    for (int i = 0; i < 8; i++) {
        const int e = i * 256 + tid;
        const int r = e >> 5, c4 = (e & 31) * 4;
        const float4 v = *(const float4*)&Os[r * 132 + c4];
        uint32_t h0, h1, l0, l1;
        split4(v, h0, h1, l0, l1);
        const size_t go = hoff + (size_t)r * SEQ + q0 + c4;
        *(uint2*)&Oh[go] = make_uint2(h0, h1);
        *(uint2*)&Ol[go] = make_uint2(l0, l1);
    }
}

// ---------------------------------------------------------------------------
extern "C" void kernel_launch(void* const* d_in, const int* in_sizes, int n_in,
                              void* d_out, int out_size)
{
    const float* q   = (const float*)d_in[0];
    const float* k   = (const float*)d_in[1];
    const float* v   = (const float*)d_in[2];
    const float* msk = (const float*)d_in[3];
    const float* Wq  = (const float*)d_in[4];
    const float* bq  = (const float*)d_in[5];
    const float* Wk  = (const float*)d_in[6];
    const float* bk  = (const float*)d_in[7];
    const float* Wv  = (const float*)d_in[8];
    const float* bv  = (const float*)d_in[9];
    const float* Wo  = (const float*)d_in[10];
    const float* bo  = (const float*)d_in[11];
    float* out = (float*)d_out;

    void *pwh, *pwl, *pxh, *pxl, *pph, *ppl, *path, *patl;
    cudaGetSymbolAddress(&pwh, g_wh);
    cudaGetSymbolAddress(&pwl, g_wl);
    cudaGetSymbolAddress(&pxh, g_xh);
    cudaGetSymbolAddress(&pxl, g_xl);
    cudaGetSymbolAddress(&pph, g_ph);
    cudaGetSymbolAddress(&ppl, g_pl);
    cudaGetSymbolAddress(&path, g_ath);
    cudaGetSymbolAddress(&patl, g_atl);

    ushort_t* wh = (ushort_t*)pwh;  ushort_t* wl = (ushort_t*)pwl;
    ushort_t* xh = (ushort_t*)pxh;  ushort_t* xl = (ushort_t*)pxl;
    ushort_t* ph = (ushort_t*)pph;  ushort_t* pl = (ushort_t*)ppl;
    ushort_t* ath = (ushort_t*)path; ushort_t* atl = (ushort_t*)patl;

    cudaFuncSetAttribute(gemm_qkv, cudaFuncAttributeMaxDynamicSharedMemorySize, GB_SMEM);
    cudaFuncSetAttribute(gemm_wo,  cudaFuncAttributeMaxDynamicSharedMemorySize, GB_SMEM);
    cudaFuncSetAttribute(attn_mma, cudaFuncAttributeMaxDynamicSharedMemorySize, AT_SMEM);

    // 1. converts
    to_hilo_w<<<dim3((unsigned)(WSZ / 1024), 4), 256>>>(Wq, Wk, Wv, Wo, wh, wl);
    to_hilo_x<<<dim3((unsigned)(XSZ / 1024), 3), 256>>>(q, k, v, xh, xl);

    // 2. merged QKV projections (Q -> fp16 hi/lo, K/V -> fp16 single)
    dim3 gq(SEQ / 128, EMB / 128, 6);
    gemm_qkv<<<gq, 256, GB_SMEM>>>(wh, wl, xh, xl, bq, bk, bv, ph, pl);

    // 3. attention
    dim3 ga(SEQ / 128, NH, BATCH);
    attn_mma<<<ga, 256, AT_SMEM>>>(ph + 0 * XSZ, pl + 0 * XSZ,
                                   ph + 1 * XSZ, ph + 2 * XSZ,
                                   msk, ath, atl);

    // 4. output projection
    dim3 go(SEQ / 128, EMB / 128, BATCH);
    gemm_wo<<<go, 256, GB_SMEM>>>(wh + 3 * WSZ, wl + 3 * WSZ, ath, atl, bo, out);
}

// round 15
// speedup vs baseline: 1.1929x; 1.1790x over previous
#include <cuda_runtime.h>
#include <cuda_fp16.h>
#include <cstdint>

#define BATCH 2
#define EMB   1024
#define SEQ   2048
#define NH    16
#define DH    64
#define KDIM  1024
#define LOG2E 1.4426950408889634f
typedef unsigned short ushort_t;

#define WSZ ((size_t)KDIM * EMB)
#define XSZ ((size_t)BATCH * EMB * SEQ)
#define ESZ ((size_t)EMB * SEQ)

// ---------------- scratch ----------------------------------------------------
__device__ ushort_t g_wh[4 * WSZ];   // weights fp16-hi
__device__ ushort_t g_wl[4 * WSZ];   // weights fp16-lo
__device__ ushort_t g_xf[3 * XSZ];   // q,k,v inputs fp16 single
__device__ ushort_t g_ph[3 * XSZ];   // Q fp16-hi, K fp16, V fp16
__device__ ushort_t g_pl[3 * XSZ];   // Q fp16-lo, (unused), (unused)
__device__ ushort_t g_atf[XSZ];      // attn out fp16 single

// ---------------- helpers ----------------------------------------------------
__device__ __forceinline__ uint32_t smem_u32(const void* p) {
    uint32_t a;
    asm("{ .reg .u64 t; cvta.to.shared.u64 t, %1; cvt.u32.u64 %0, t; }" : "=r"(a) : "l"(p));
    return a;
}
__device__ __forceinline__ void mma16816f(float* c, const uint32_t* a, const uint32_t* b) {
    asm volatile("mma.sync.aligned.m16n8k16.row.col.f32.f16.f16.f32 "
        "{%0,%1,%2,%3}, {%4,%5,%6,%7}, {%8,%9}, {%0,%1,%2,%3};"
        : "+f"(c[0]), "+f"(c[1]), "+f"(c[2]), "+f"(c[3])
        : "r"(a[0]), "r"(a[1]), "r"(a[2]), "r"(a[3]), "r"(b[0]), "r"(b[1]));
}
#define LDSM_X4(r0,r1,r2,r3,addr) \
    asm volatile("ldmatrix.sync.aligned.m8n8.x4.shared.b16 {%0,%1,%2,%3}, [%4];" \
                 : "=r"(r0),"=r"(r1),"=r"(r2),"=r"(r3) : "r"(addr))
#define LDSM_X4T(r0,r1,r2,r3,addr) \
    asm volatile("ldmatrix.sync.aligned.m8n8.x4.trans.shared.b16 {%0,%1,%2,%3}, [%4];" \
                 : "=r"(r0),"=r"(r1),"=r"(r2),"=r"(r3) : "r"(addr))
#define CVT_F16X2(res,a,b)  asm("cvt.rn.f16x2.f32 %0, %1, %2;" : "=r"(res) : "f"(b), "f"(a))
#define EX2F(y,x) asm("ex2.approx.f32 %0, %1;" : "=f"(y) : "f"(x))
#define CP_ASYNC16(dst, src) \
    asm volatile("cp.async.cg.shared.global [%0], [%1], 16;" :: "r"(dst), "l"(src) : "memory")
#define CP_COMMIT() asm volatile("cp.async.commit_group;" ::: "memory")
#define CP_WAIT(n) asm volatile("cp.async.wait_group %0;" :: "n"(n) : "memory")

// fp16 hi/lo split of a float4
__device__ __forceinline__ void split4_f16(const float4 v, uint32_t& h0, uint32_t& h1,
                                           uint32_t& l0, uint32_t& l1) {
    CVT_F16X2(h0, v.x, v.y);
    CVT_F16X2(h1, v.z, v.w);
    const __half2 hx = *(const __half2*)&h0;
    const __half2 hy = *(const __half2*)&h1;
    const float r0 = v.x - __half2float(__low2half(hx));
    const float r1 = v.y - __half2float(__high2half(hx));
    const float r2 = v.z - __half2float(__low2half(hy));
    const float r3 = v.w - __half2float(__high2half(hy));
    CVT_F16X2(l0, r0, r1);
    CVT_F16X2(l1, r2, r3);
}

// ---------------- converts ----------------------------------------------------
__global__ void __launch_bounds__(256) conv_w(
    const float* __restrict__ w0, const float* __restrict__ w1,
    const float* __restrict__ w2, const float* __restrict__ w3,
    ushort_t* __restrict__ hi, ushort_t* __restrict__ lo)
{
    const int g = blockIdx.y;
    const float* src = g == 0 ? w0 : (g == 1 ? w1 : (g == 2 ? w2 : w3));
    const size_t i = ((size_t)blockIdx.x * 256 + threadIdx.x) * 4;
    const float4 v = *(const float4*)&src[i];
    uint32_t h0, h1, l0, l1;
    split4_f16(v, h0, h1, l0, l1);
    *(uint2*)&hi[g * WSZ + i] = make_uint2(h0, h1);
    *(uint2*)&lo[g * WSZ + i] = make_uint2(l0, l1);
}
__global__ void __launch_bounds__(256) conv_x(
    const float* __restrict__ x0, const float* __restrict__ x1,
    const float* __restrict__ x2, ushort_t* __restrict__ xf)
{
    const int g = blockIdx.y;
    const float* src = g == 0 ? x0 : (g == 1 ? x1 : x2);
    const size_t i = ((size_t)blockIdx.x * 256 + threadIdx.x) * 4;
    const float4 v = *(const float4*)&src[i];
    uint32_t f0, f1;
    CVT_F16X2(f0, v.x, v.y);
    CVT_F16X2(f1, v.z, v.w);
    *(uint2*)&xf[g * XSZ + i] = make_uint2(f0, f1);
}

// ---------------- GEMM body: 2-pass fp16 (A = W hi/lo, B = X single) ----------
// mode: 0 = f32 out, 2 = fp16 single out, 3 = fp16 hi/lo out
#define LAH 56
#define LBH 136
#define G_AH 0
#define G_AL 14336
#define G_BF 28672
#define G_BUF 37376
#define G_BIAS 74752
#define GB_SMEM 75264

__device__ __forceinline__ void gemm_body(
    const ushort_t* __restrict__ Ah, const ushort_t* __restrict__ Al,
    const ushort_t* __restrict__ Bf,
    const float* __restrict__ bias, float* __restrict__ Cf,
    ushort_t* __restrict__ Ch, ushort_t* __restrict__ Cl,
    float alpha, int mode)
{
    extern __shared__ char smg[];
    const uint32_t sb = smem_u32(smg);
    const int tid = threadIdx.x, wid = tid >> 5, lane = tid & 31;
    const int n0 = blockIdx.x * 128, m0 = blockIdx.y * 128;
    float* bias_s = (float*)(smg + G_BIAS);
    if (tid < 128) bias_s[tid] = bias[m0 + tid];

    const int wm = wid & 3, wn = wid >> 2;
    float acc[2][8][4];
#pragma unroll
    for (int ms = 0; ms < 2; ms++)
#pragma unroll
        for (int nt = 0; nt < 8; nt++)
#pragma unroll
            for (int i = 0; i < 4; i++) acc[ms][nt][i] = 0.f;

    const int arow = lane & 15, ak8 = (lane >> 4) * 8;
    const int bj = lane >> 3, br = lane & 7;
    const int bk = (bj & 1) * 8 + br, bn8 = (bj >> 1) * 8;

#define G_CP(kt, buf) do {                                                     \
    const uint32_t base = sb + (buf) * G_BUF;                                  \
    _Pragma("unroll")                                                          \
    for (int i = 0; i < 2; i++) {                                              \
        const int id = i * 256 + tid;                                          \
        const int r = id >> 2, c = id & 3;                                     \
        const size_t so = (size_t)(m0 + r) * KDIM + (kt) * 32 + c * 8;         \
        const uint32_t doff = (uint32_t)(r * 112 + c * 16);                    \
        CP_ASYNC16(base + G_AH + doff, Ah + so);                               \
        CP_ASYNC16(base + G_AL + doff, Al + so);                               \
    }                                                                          \
    _Pragma("unroll")                                                          \
    for (int i = 0; i < 2; i++) {                                              \
        const int id = i * 256 + tid;                                          \
        const int r = id >> 4, c = id & 15;                                    \
        const size_t so = (size_t)((kt) * 32 + r) * SEQ + n0 + c * 8;          \
        const uint32_t doff = (uint32_t)(r * 272 + c * 16);                    \
        CP_ASYNC16(base + G_BF + doff, Bf + so);                               \
    }                                                                          \
} while (0)

    G_CP(0, 0);
    CP_COMMIT();

    const int NKT = KDIM / 32;
    for (int kt = 0; kt < NKT; kt++) {
        __syncthreads();
        if (kt + 1 < NKT) { G_CP(kt + 1, (kt + 1) & 1); CP_COMMIT(); CP_WAIT(1); }
        else CP_WAIT(0);
        __syncthreads();

        const uint32_t base = sb + (kt & 1) * G_BUF;
#pragma unroll
        for (int ks = 0; ks < 2; ks++) {
            uint32_t aF[2][4], aL[2][4];
#pragma unroll
            for (int ms = 0; ms < 2; ms++) {
                const uint32_t ao = (uint32_t)((wm * 32 + ms * 16 + arow) * LAH + ks * 16 + ak8) * 2;
                LDSM_X4(aF[ms][0], aF[ms][1], aF[ms][2], aF[ms][3], base + G_AH + ao);
                LDSM_X4(aL[ms][0], aL[ms][1], aL[ms][2], aL[ms][3], base + G_AL + ao);
            }
#pragma unroll
            for (int nt16 = 0; nt16 < 4; nt16++) {
                uint32_t bF[4];
                const uint32_t bo = (uint32_t)((ks * 16 + bk) * LBH + wn * 64 + nt16 * 16 + bn8) * 2;
                LDSM_X4T(bF[0], bF[1], bF[2], bF[3], base + G_BF + bo);
#pragma unroll
                for (int ms = 0; ms < 2; ms++)
#pragma unroll
                    for (int s = 0; s < 2; s++) {
                        float* a4 = acc[ms][nt16 * 2 + s];
                        mma16816f(a4, aF[ms], &bF[s * 2]);
                        mma16816f(a4, aL[ms], &bF[s * 2]);
                    }
            }
        }
    }

    __syncthreads();
    float* Cs = (float*)smg;
    {
        const int rr = lane >> 2, cc = (lane & 3) * 2;
#pragma unroll
        for (int ms = 0; ms < 2; ms++)
#pragma unroll
            for (int nt = 0; nt < 8; nt++) {
                const int r = wm * 32 + ms * 16 + rr;
                const int c = wn * 64 + nt * 8 + cc;
                Cs[r * 132 + c]           = acc[ms][nt][0];
                Cs[r * 132 + c + 1]       = acc[ms][nt][1];
                Cs[(r + 8) * 132 + c]     = acc[ms][nt][2];
                Cs[(r + 8) * 132 + c + 1] = acc[ms][nt][3];
            }
    }
    __syncthreads();
#pragma unroll
    for (int i = 0; i < 16; i++) {
        const int e = i * 256 + tid;
        const int r = e >> 5, c4 = (e & 31) * 4;
        float4 v = *(const float4*)&Cs[r * 132 + c4];
        const float bi = bias_s[r];
        v.x = alpha * (v.x + bi); v.y = alpha * (v.y + bi);
        v.z = alpha * (v.z + bi); v.w = alpha * (v.w + bi);
        const size_t go = (size_t)(m0 + r) * SEQ + n0 + c4;
        if (mode == 0) {
            *(float4*)&Cf[go] = v;
        } else if (mode == 2) {
            uint32_t f0, f1;
            CVT_F16X2(f0, v.x, v.y);
            CVT_F16X2(f1, v.z, v.w);
            *(uint2*)&Ch[go] = make_uint2(f0, f1);
        } else {
            uint32_t h0, h1, l0, l1;
            split4_f16(v, h0, h1, l0, l1);
            *(uint2*)&Ch[go] = make_uint2(h0, h1);
            *(uint2*)&Cl[go] = make_uint2(l0, l1);
        }
    }
}

__global__ void __launch_bounds__(256, 2) gemm_qkv(
    const ushort_t* __restrict__ wh, const ushort_t* __restrict__ wl,
    const ushort_t* __restrict__ xf,
    const float* __restrict__ bq, const float* __restrict__ bk,
    const float* __restrict__ bv,
    ushort_t* __restrict__ ph, ushort_t* __restrict__ pl)
{
    const int gi = blockIdx.z >> 1, bb = blockIdx.z & 1;
    const size_t woff = (size_t)gi * WSZ;
    const size_t xoff = (size_t)gi * XSZ + (size_t)bb * ESZ;
    const float* bias = gi == 0 ? bq : (gi == 1 ? bk : bv);
    const float alpha = gi == 0 ? 0.125f * LOG2E : 1.0f;
    const int mode = gi == 0 ? 3 : 2;   // Q -> fp16 hi/lo, K/V -> fp16 single
    gemm_body(wh + woff, wl + woff, xf + xoff, bias,
              nullptr, ph + xoff, pl + xoff, alpha, mode);
}
__global__ void __launch_bounds__(256, 2) gemm_wo(
    const ushort_t* __restrict__ wh, const ushort_t* __restrict__ wl,
    const ushort_t* __restrict__ af,
    const float* __restrict__ bo, float* __restrict__ out)
{
    const size_t off = (size_t)blockIdx.z * ESZ;
    gemm_body(wh, wl, af + off, bo, out + off, nullptr, nullptr, 1.0f, 0);
}

// ---------------- flash attention (unchanged math from R12/R14) --------------
#define PKH 136
#define KVA 17408            // one array (64 x 136 halves)
#define KVB2 34816           // buffer: Kf, Vf
#define MASK_OFF 69632       // 128 x 132 f32 = 67584 B
#define AT_SMEM 137216       // = MASK_OFF + 67584

__global__ void __launch_bounds__(256) attn_mma(
    const ushort_t* __restrict__ Qh, const ushort_t* __restrict__ Ql,
    const ushort_t* __restrict__ Kf, const ushort_t* __restrict__ Vf,
    const float* __restrict__ MASK,
    ushort_t* __restrict__ Of)
{
    extern __shared__ char sma[];
    const uint32_t sb = smem_u32(sma);
    const int tid = threadIdx.x, wid = tid >> 5, lane = tid & 31;
    const int b = blockIdx.z, h = blockIdx.y, q0 = blockIdx.x * 128;

    const size_t hoff = ((size_t)b * EMB + h * DH) * SEQ;
    const float* Mg = MASK + (size_t)b * SEQ * SEQ;

#define A_CPKV(k0, buf) do {                                                   \
    const uint32_t base = sb + (buf) * KVB2;                                   \
    _Pragma("unroll")                                                          \
    for (int i = 0; i < 4; i++) {                                              \
        const int id = i * 256 + tid;                                          \
        const int r = id >> 4, c = id & 15;                                    \
        const size_t so = hoff + (size_t)r * SEQ + (k0) + c * 8;               \
        const uint32_t doff = (uint32_t)(r * 272 + c * 16);                    \
        CP_ASYNC16(base +       doff, Kf + so);                                \
        CP_ASYNC16(base + KVA + doff, Vf + so);                                \
    }                                                                          \
} while (0)

#define A_CPMASK(k0) do {                                                      \
    const uint32_t mb = sb + MASK_OFF;                                         \
    _Pragma("unroll")                                                          \
    for (int i = 0; i < 16; i++) {                                             \
        const int id = i * 256 + tid;                                          \
        const int r = id >> 5, c32 = id & 31;                                  \
        CP_ASYNC16(mb + (uint32_t)(r * 132 + c32 * 4) * 4,                     \
                   Mg + (size_t)((k0) + r) * SEQ + q0 + c32 * 4);              \
    }                                                                          \
} while (0)

    {
        const uint32_t qb = sb + KVB2;
#pragma unroll
        for (int i = 0; i < 4; i++) {
            const int id = i * 256 + tid;
            const int r = id >> 4, c = id & 15;
            const size_t so = hoff + (size_t)r * SEQ + q0 + c * 8;
            const uint32_t doff = (uint32_t)(r * 272 + c * 16);
            CP_ASYNC16(qb + doff, Qh + so);
            CP_ASYNC16(qb + KVA + doff, Ql + so);
        }
    }
    A_CPMASK(0);
    CP_COMMIT();
    A_CPKV(0, 0);
    CP_COMMIT();
    CP_WAIT(1);
    __syncthreads();

    const int arow_k = (lane & 7) + ((lane >> 4) << 3);
    const int amcol  = ((lane >> 3) & 1) * 8;
    uint32_t qfh[4][4], qfl[4][4];
#pragma unroll
    for (int ks = 0; ks < 4; ks++) {
        const uint32_t ao = (uint32_t)((ks * 16 + arow_k) * PKH + wid * 16 + amcol) * 2;
        LDSM_X4T(qfh[ks][0], qfh[ks][1], qfh[ks][2], qfh[ks][3], sb + KVB2 + ao);
        LDSM_X4T(qfl[ks][0], qfl[ks][1], qfl[ks][2], qfl[ks][3], sb + KVB2 + KVA + ao);
    }
    __syncthreads();

    const int bj = lane >> 3, br = lane & 7;
    const int bk = (bj & 1) * 8 + br, bn8 = (bj >> 1) * 8;
    const int bvrow = ((lane >> 4) & 1) * 8 + br;
    const int bvk8  = ((lane >> 3) & 1) * 8;

    float o[8][4];
#pragma unroll
    for (int d = 0; d < 8; d++)
#pragma unroll
        for (int j = 0; j < 4; j++) o[d][j] = 0.f;
    float lsum0 = 0.f, lsum1 = 0.f;

    const int qr = wid * 16 + (lane >> 2);
    const int krow2 = 2 * (lane & 3);
    const float* Ms = (const float*)(sma + MASK_OFF);

    const int NT = SEQ / 128;
    for (int kt = 0; kt < NT; kt++) {
        CP_WAIT(0);
        __syncthreads();

        const uint32_t kvb = sb + (kt & 1) * KVB2;

        float s[16][4];
#pragma unroll
        for (int nt = 0; nt < 16; nt++) {
            const float* mp = Ms + (nt * 8 + krow2) * 132 + qr;
            s[nt][0] = mp[0]   * LOG2E;
            s[nt][1] = mp[132] * LOG2E;
            s[nt][2] = mp[8]   * LOG2E;
            s[nt][3] = mp[140] * LOG2E;
        }
        __syncthreads();

        if (kt + 1 < NT) {
            A_CPKV((kt + 1) * 128, (kt + 1) & 1);
            A_CPMASK((kt + 1) * 128);
            CP_COMMIT();
        }

#pragma unroll
        for (int h2 = 0; h2 < 2; h2++)
#pragma unroll
            for (int ks = 0; ks < 4; ks++)
#pragma unroll
                for (int np = 0; np < 4; np++) {
                    uint32_t kf[4];
                    const uint32_t bo = (uint32_t)((ks * 16 + bk) * PKH
                                                   + h2 * 64 + np * 16 + bn8) * 2;
                    LDSM_X4T(kf[0], kf[1], kf[2], kf[3], kvb + bo);
#pragma unroll
                    for (int s2 = 0; s2 < 2; s2++) {
                        float* a4 = s[h2 * 8 + np * 2 + s2];
                        mma16816f(a4, qfh[ks], &kf[s2 * 2]);
                        mma16816f(a4, qfl[ks], &kf[s2 * 2]);
                    }
                }

#pragma unroll
        for (int h2 = 0; h2 < 2; h2++) {
            float* sh = &s[h2 * 8][0];
            float rs0 = 0.f, rs1 = 0.f;
#pragma unroll
            for (int nt = 0; nt < 8; nt++) {
                float* sn = sh + nt * 4;
#pragma unroll
                for (int j = 0; j < 4; j++) EX2F(sn[j], sn[j]);
                rs0 += sn[0] + sn[1];
                rs1 += sn[2] + sn[3];
            }
            rs0 += __shfl_xor_sync(0xffffffffu, rs0, 1);
            rs0 += __shfl_xor_sync(0xffffffffu, rs0, 2);
            rs1 += __shfl_xor_sync(0xffffffffu, rs1, 1);
            rs1 += __shfl_xor_sync(0xffffffffu, rs1, 2);
            lsum0 += rs0;
            lsum1 += rs1;

            uint32_t pa[4][4];
#pragma unroll
            for (int ks = 0; ks < 4; ks++) {
                const float* u = sh + ks * 8;
                const float* w = sh + ks * 8 + 4;
                CVT_F16X2(pa[ks][0], u[0], u[1]);
                CVT_F16X2(pa[ks][1], u[2], u[3]);
                CVT_F16X2(pa[ks][2], w[0], w[1]);
                CVT_F16X2(pa[ks][3], w[2], w[3]);
            }
#pragma unroll
            for (int ks = 0; ks < 4; ks++)
#pragma unroll
                for (int dp = 0; dp < 4; dp++) {
                    uint32_t vf[4];
                    const uint32_t bo = (uint32_t)((dp * 16 + bvrow) * PKH
                                                   + h2 * 64 + ks * 16 + bvk8) * 2;
                    LDSM_X4(vf[0], vf[1], vf[2], vf[3], kvb + KVA + bo);
#pragma unroll
                    for (int s2 = 0; s2 < 2; s2++)
                        mma16816f(o[dp * 2 + s2], pa[ks], &vf[s2 * 2]);
                }
        }
    }

    // ---- normalize, transpose via smem, fp16-single coalesced store ----
    const float inv0 = 1.f / lsum0, inv1 = 1.f / lsum1;
    __syncthreads();
    float* Os = (float*)sma;   // [64 dh][132]
#pragma unroll
    for (int d = 0; d < 8; d++) {
        const int dc = d * 8 + krow2;
        Os[dc * 132 + qr]           = o[d][0] * inv0;
        Os[(dc + 1) * 132 + qr]     = o[d][1] * inv0;
        Os[dc * 132 + qr + 8]       = o[d][2] * inv1;
        Os[(dc + 1) * 132 + qr + 8] = o[d][3] * inv1;
    }
    __syncthreads();
#pragma unroll
    for (int i = 0; i < 8; i++) {
        const int e = i * 256 + tid;
        const int r = e >> 5, c4 = (e & 31) * 4;
        const float4 v = *(const float4*)&Os[r * 132 + c4];
        uint32_t f0, f1;
        CVT_F16X2(f0, v.x, v.y);
        CVT_F16X2(f1, v.z, v.w);
        *(uint2*)&Of[hoff + (size_t)r * SEQ + q0 + c4] = make_uint2(f0, f1);
    }
}

// ---------------------------------------------------------------------------
extern "C" void kernel_launch(void* const* d_in, const int* in_sizes, int n_in,
                              void* d_out, int out_size)
{
    const float* q   = (const float*)d_in[0];
    const float* k   = (const float*)d_in[1];
    const float* v   = (const float*)d_in[2];
    const float* msk = (const float*)d_in[3];
    const float* Wq  = (const float*)d_in[4];
    const float* bq  = (const float*)d_in[5];
    const float* Wk  = (const float*)d_in[6];
    const float* bk  = (const float*)d_in[7];
    const float* Wv  = (const float*)d_in[8];
    const float* bv  = (const float*)d_in[9];
    const float* Wo  = (const float*)d_in[10];
    const float* bo  = (const float*)d_in[11];
    float* out = (float*)d_out;

    void *pwh, *pwl, *pxf, *pph, *ppl, *patf;
    cudaGetSymbolAddress(&pwh, g_wh);
    cudaGetSymbolAddress(&pwl, g_wl);
    cudaGetSymbolAddress(&pxf, g_xf);
    cudaGetSymbolAddress(&pph, g_ph);
    cudaGetSymbolAddress(&ppl, g_pl);
    cudaGetSymbolAddress(&patf, g_atf);

    ushort_t* wh = (ushort_t*)pwh;  ushort_t* wl = (ushort_t*)pwl;
    ushort_t* xf = (ushort_t*)pxf;
    ushort_t* ph = (ushort_t*)pph;  ushort_t* pl = (ushort_t*)ppl;
    ushort_t* atf = (ushort_t*)patf;

    cudaFuncSetAttribute(gemm_qkv, cudaFuncAttributeMaxDynamicSharedMemorySize, GB_SMEM);
    cudaFuncSetAttribute(gemm_wo,  cudaFuncAttributeMaxDynamicSharedMemorySize, GB_SMEM);
    cudaFuncSetAttribute(attn_mma, cudaFuncAttributeMaxDynamicSharedMemorySize, AT_SMEM);

    // 1. converts (weights fp16 hi/lo; inputs fp16 single)
    conv_w<<<dim3((unsigned)(WSZ / 1024), 4), 256>>>(Wq, Wk, Wv, Wo, wh, wl);
    conv_x<<<dim3((unsigned)(XSZ / 1024), 3), 256>>>(q, k, v, xf);

    // 2. merged QKV projections (2-pass fp16)
    dim3 gq(SEQ / 128, EMB / 128, 6);
    gemm_qkv<<<gq, 256, GB_SMEM>>>(wh, wl, xf, bq, bk, bv, ph, pl);

    // 3. attention
    dim3 ga(SEQ / 128, NH, BATCH);
    attn_mma<<<ga, 256, AT_SMEM>>>(ph + 0 * XSZ, pl + 0 * XSZ,
                                   ph + 1 * XSZ, ph + 2 * XSZ,
                                   msk, atf);

    // 4. output projection (2-pass fp16)
    dim3 go(SEQ / 128, EMB / 128, BATCH);
    gemm_wo<<<go, 256, GB_SMEM>>>(wh + 3 * WSZ, wl + 3 * WSZ, atf, bo, out);
}

// round 16
// speedup vs baseline: 1.3044x; 1.0935x over previous
#include <cuda_runtime.h>
#include <cuda_fp16.h>
#include <cstdint>

#define BATCH 2
#define EMB   1024
#define SEQ   2048
#define NH    16
#define DH    64
#define KDIM  1024
#define LOG2E 1.4426950408889634f
typedef unsigned short ushort_t;

#define WSZ ((size_t)KDIM * EMB)
#define XSZ ((size_t)BATCH * EMB * SEQ)
#define ESZ ((size_t)EMB * SEQ)

// ---------------- scratch ----------------------------------------------------
__device__ ushort_t g_wh[4 * WSZ];   // weights fp16-hi
__device__ ushort_t g_wl[4 * WSZ];   // weights fp16-lo
__device__ ushort_t g_xf[3 * XSZ];   // q,k,v inputs fp16 single
__device__ ushort_t g_pf[3 * XSZ];   // Q, K, V projections fp16 single
__device__ ushort_t g_atf[XSZ];      // attn out fp16 single

// ---------------- helpers ----------------------------------------------------
__device__ __forceinline__ uint32_t smem_u32(const void* p) {
    uint32_t a;
    asm("{ .reg .u64 t; cvta.to.shared.u64 t, %1; cvt.u32.u64 %0, t; }" : "=r"(a) : "l"(p));
    return a;
}
__device__ __forceinline__ void mma16816f(float* c, const uint32_t* a, const uint32_t* b) {
    asm volatile("mma.sync.aligned.m16n8k16.row.col.f32.f16.f16.f32 "
        "{%0,%1,%2,%3}, {%4,%5,%6,%7}, {%8,%9}, {%0,%1,%2,%3};"
        : "+f"(c[0]), "+f"(c[1]), "+f"(c[2]), "+f"(c[3])
        : "r"(a[0]), "r"(a[1]), "r"(a[2]), "r"(a[3]), "r"(b[0]), "r"(b[1]));
}
#define LDSM_X4(r0,r1,r2,r3,addr) \
    asm volatile("ldmatrix.sync.aligned.m8n8.x4.shared.b16 {%0,%1,%2,%3}, [%4];" \
                 : "=r"(r0),"=r"(r1),"=r"(r2),"=r"(r3) : "r"(addr))
#define LDSM_X4T(r0,r1,r2,r3,addr) \
    asm volatile("ldmatrix.sync.aligned.m8n8.x4.trans.shared.b16 {%0,%1,%2,%3}, [%4];" \
                 : "=r"(r0),"=r"(r1),"=r"(r2),"=r"(r3) : "r"(addr))
#define CVT_F16X2(res,a,b)  asm("cvt.rn.f16x2.f32 %0, %1, %2;" : "=r"(res) : "f"(b), "f"(a))
#define EX2F(y,x) asm("ex2.approx.f32 %0, %1;" : "=f"(y) : "f"(x))
#define CP_ASYNC16(dst, src) \
    asm volatile("cp.async.cg.shared.global [%0], [%1], 16;" :: "r"(dst), "l"(src) : "memory")
#define CP_COMMIT() asm volatile("cp.async.commit_group;" ::: "memory")
#define CP_WAIT(n) asm volatile("cp.async.wait_group %0;" :: "n"(n) : "memory")

// fp16 hi/lo split of a float4
__device__ __forceinline__ void split4_f16(const float4 v, uint32_t& h0, uint32_t& h1,
                                           uint32_t& l0, uint32_t& l1) {
    CVT_F16X2(h0, v.x, v.y);
    CVT_F16X2(h1, v.z, v.w);
    const __half2 hx = *(const __half2*)&h0;
    const __half2 hy = *(const __half2*)&h1;
    const float r0 = v.x - __half2float(__low2half(hx));
    const float r1 = v.y - __half2float(__high2half(hx));
    const float r2 = v.z - __half2float(__low2half(hy));
    const float r3 = v.w - __half2float(__high2half(hy));
    CVT_F16X2(l0, r0, r1);
    CVT_F16X2(l1, r2, r3);
}

// ---------------- converts ----------------------------------------------------
__global__ void __launch_bounds__(256) conv_w(
    const float* __restrict__ w0, const float* __restrict__ w1,
    const float* __restrict__ w2, const float* __restrict__ w3,
    ushort_t* __restrict__ hi, ushort_t* __restrict__ lo)
{
    const int g = blockIdx.y;
    const float* src = g == 0 ? w0 : (g == 1 ? w1 : (g == 2 ? w2 : w3));
    const size_t i = ((size_t)blockIdx.x * 256 + threadIdx.x) * 4;
    const float4 v = *(const float4*)&src[i];
    uint32_t h0, h1, l0, l1;
    split4_f16(v, h0, h1, l0, l1);
    *(uint2*)&hi[g * WSZ + i] = make_uint2(h0, h1);
    *(uint2*)&lo[g * WSZ + i] = make_uint2(l0, l1);
}
__global__ void __launch_bounds__(256) conv_x(
    const float* __restrict__ x0, const float* __restrict__ x1,
    const float* __restrict__ x2, ushort_t* __restrict__ xf)
{
    const int g = blockIdx.y;
    const float* src = g == 0 ? x0 : (g == 1 ? x1 : x2);
    const size_t i = ((size_t)blockIdx.x * 256 + threadIdx.x) * 4;
    const float4 v = *(const float4*)&src[i];
    uint32_t f0, f1;
    CVT_F16X2(f0, v.x, v.y);
    CVT_F16X2(f1, v.z, v.w);
    *(uint2*)&xf[g * XSZ + i] = make_uint2(f0, f1);
}

// ---------------- GEMM body: 2-pass fp16 (A = W hi/lo, B = X single) ----------
// mode: 0 = f32 out, 2 = fp16 single out
#define LAH 56
#define LBH 136
#define G_AH 0
#define G_AL 14336
#define G_BF 28672
#define G_BUF 37376
#define G_BIAS 74752
#define GB_SMEM 75264

__device__ __forceinline__ void gemm_body(
    const ushort_t* __restrict__ Ah, const ushort_t* __restrict__ Al,
    const ushort_t* __restrict__ Bf,
    const float* __restrict__ bias, float* __restrict__ Cf,
    ushort_t* __restrict__ Ch, float alpha, int mode)
{
    extern __shared__ char smg[];
    const uint32_t sb = smem_u32(smg);
    const int tid = threadIdx.x, wid = tid >> 5, lane = tid & 31;
    const int n0 = blockIdx.x * 128, m0 = blockIdx.y * 128;
    float* bias_s = (float*)(smg + G_BIAS);
    if (tid < 128) bias_s[tid] = bias[m0 + tid];

    const int wm = wid & 3, wn = wid >> 2;
    float acc[2][8][4];
#pragma unroll
    for (int ms = 0; ms < 2; ms++)
#pragma unroll
        for (int nt = 0; nt < 8; nt++)
#pragma unroll
            for (int i = 0; i < 4; i++) acc[ms][nt][i] = 0.f;

    const int arow = lane & 15, ak8 = (lane >> 4) * 8;
    const int bj = lane >> 3, br = lane & 7;
    const int bk = (bj & 1) * 8 + br, bn8 = (bj >> 1) * 8;

#define G_CP(kt, buf) do {                                                     \
    const uint32_t base = sb + (buf) * G_BUF;                                  \
    _Pragma("unroll")                                                          \
    for (int i = 0; i < 2; i++) {                                              \
        const int id = i * 256 + tid;                                          \
        const int r = id >> 2, c = id & 3;                                     \
        const size_t so = (size_t)(m0 + r) * KDIM + (kt) * 32 + c * 8;         \
        const uint32_t doff = (uint32_t)(r * 112 + c * 16);                    \
        CP_ASYNC16(base + G_AH + doff, Ah + so);                               \
        CP_ASYNC16(base + G_AL + doff, Al + so);                               \
    }                                                                          \
    _Pragma("unroll")                                                          \
    for (int i = 0; i < 2; i++) {                                              \
        const int id = i * 256 + tid;                                          \
        const int r = id >> 4, c = id & 15;                                    \
        const size_t so = (size_t)((kt) * 32 + r) * SEQ + n0 + c * 8;          \
        const uint32_t doff = (uint32_t)(r * 272 + c * 16);                    \
        CP_ASYNC16(base + G_BF + doff, Bf + so);                               \
    }                                                                          \
} while (0)

    G_CP(0, 0);
    CP_COMMIT();

    const int NKT = KDIM / 32;
    for (int kt = 0; kt < NKT; kt++) {
        __syncthreads();
        if (kt + 1 < NKT) { G_CP(kt + 1, (kt + 1) & 1); CP_COMMIT(); CP_WAIT(1); }
        else CP_WAIT(0);
        __syncthreads();

        const uint32_t base = sb + (kt & 1) * G_BUF;
#pragma unroll
        for (int ks = 0; ks < 2; ks++) {
            uint32_t aF[2][4], aL[2][4];
#pragma unroll
            for (int ms = 0; ms < 2; ms++) {
                const uint32_t ao = (uint32_t)((wm * 32 + ms * 16 + arow) * LAH + ks * 16 + ak8) * 2;
                LDSM_X4(aF[ms][0], aF[ms][1], aF[ms][2], aF[ms][3], base + G_AH + ao);
                LDSM_X4(aL[ms][0], aL[ms][1], aL[ms][2], aL[ms][3], base + G_AL + ao);
            }
#pragma unroll
            for (int nt16 = 0; nt16 < 4; nt16++) {
                uint32_t bF[4];
                const uint32_t bo = (uint32_t)((ks * 16 + bk) * LBH + wn * 64 + nt16 * 16 + bn8) * 2;
                LDSM_X4T(bF[0], bF[1], bF[2], bF[3], base + G_BF + bo);
#pragma unroll
                for (int ms = 0; ms < 2; ms++)
#pragma unroll
                    for (int s = 0; s < 2; s++) {
                        float* a4 = acc[ms][nt16 * 2 + s];
                        mma16816f(a4, aF[ms], &bF[s * 2]);
                        mma16816f(a4, aL[ms], &bF[s * 2]);
                    }
            }
        }
    }

    __syncthreads();
    float* Cs = (float*)smg;
    {
        const int rr = lane >> 2, cc = (lane & 3) * 2;
#pragma unroll
        for (int ms = 0; ms < 2; ms++)
#pragma unroll
            for (int nt = 0; nt < 8; nt++) {
                const int r = wm * 32 + ms * 16 + rr;
                const int c = wn * 64 + nt * 8 + cc;
                Cs[r * 132 + c]           = acc[ms][nt][0];
                Cs[r * 132 + c + 1]       = acc[ms][nt][1];
                Cs[(r + 8) * 132 + c]     = acc[ms][nt][2];
                Cs[(r + 8) * 132 + c + 1] = acc[ms][nt][3];
            }
    }
    __syncthreads();
#pragma unroll
    for (int i = 0; i < 16; i++) {
        const int e = i * 256 + tid;
        const int r = e >> 5, c4 = (e & 31) * 4;
        float4 v = *(const float4*)&Cs[r * 132 + c4];
        const float bi = bias_s[r];
        v.x = alpha * (v.x + bi); v.y = alpha * (v.y + bi);
        v.z = alpha * (v.z + bi); v.w = alpha * (v.w + bi);
        const size_t go = (size_t)(m0 + r) * SEQ + n0 + c4;
        if (mode == 0) {
            *(float4*)&Cf[go] = v;
        } else {
            uint32_t f0, f1;
            CVT_F16X2(f0, v.x, v.y);
            CVT_F16X2(f1, v.z, v.w);
            *(uint2*)&Ch[go] = make_uint2(f0, f1);
        }
    }
}

__global__ void __launch_bounds__(256, 2) gemm_qkv(
    const ushort_t* __restrict__ wh, const ushort_t* __restrict__ wl,
    const ushort_t* __restrict__ xf,
    const float* __restrict__ bq, const float* __restrict__ bk,
    const float* __restrict__ bv, ushort_t* __restrict__ pf)
{
    const int gi = blockIdx.z >> 1, bb = blockIdx.z & 1;
    const size_t woff = (size_t)gi * WSZ;
    const size_t xoff = (size_t)gi * XSZ + (size_t)bb * ESZ;
    const float* bias = gi == 0 ? bq : (gi == 1 ? bk : bv);
    const float alpha = gi == 0 ? 0.125f * LOG2E : 1.0f;
    gemm_body(wh + woff, wl + woff, xf + xoff, bias,
              nullptr, pf + xoff, alpha, 2);
}
__global__ void __launch_bounds__(256, 2) gemm_wo(
    const ushort_t* __restrict__ wh, const ushort_t* __restrict__ wl,
    const ushort_t* __restrict__ af,
    const float* __restrict__ bo, float* __restrict__ out)
{
    const size_t off = (size_t)blockIdx.z * ESZ;
    gemm_body(wh, wl, af + off, bo, out + off, nullptr, 1.0f, 0);
}

// ---------------- flash attention: all-fp16 single-pass QK and PV ------------
#define PKH 136
#define KVA 17408            // one array (64 x 136 halves)
#define KVB2 34816           // buffer: Kf, Vf
#define MASK_OFF 69632       // 128 x 132 f32 = 67584 B
#define AT_SMEM 137216       // = MASK_OFF + 67584

__global__ void __launch_bounds__(256) attn_mma(
    const ushort_t* __restrict__ Qf,
    const ushort_t* __restrict__ Kf, const ushort_t* __restrict__ Vf,
    const float* __restrict__ MASK,
    ushort_t* __restrict__ Of)
{
    extern __shared__ char sma[];
    const uint32_t sb = smem_u32(sma);
    const int tid = threadIdx.x, wid = tid >> 5, lane = tid & 31;
    const int b = blockIdx.z, h = blockIdx.y, q0 = blockIdx.x * 128;

    const size_t hoff = ((size_t)b * EMB + h * DH) * SEQ;
    const float* Mg = MASK + (size_t)b * SEQ * SEQ;

#define A_CPKV(k0, buf) do {                                                   \
    const uint32_t base = sb + (buf) * KVB2;                                   \
    _Pragma("unroll")                                                          \
    for (int i = 0; i < 4; i++) {                                              \
        const int id = i * 256 + tid;                                          \
        const int r = id >> 4, c = id & 15;                                    \
        const size_t so = hoff + (size_t)r * SEQ + (k0) + c * 8;               \
        const uint32_t doff = (uint32_t)(r * 272 + c * 16);                    \
        CP_ASYNC16(base +       doff, Kf + so);                                \
        CP_ASYNC16(base + KVA + doff, Vf + so);                                \
    }                                                                          \
} while (0)

#define A_CPMASK(k0) do {                                                      \
    const uint32_t mb = sb + MASK_OFF;                                         \
    _Pragma("unroll")                                                          \
    for (int i = 0; i < 16; i++) {                                             \
        const int id = i * 256 + tid;                                          \
        const int r = id >> 5, c32 = id & 31;                                  \
        CP_ASYNC16(mb + (uint32_t)(r * 132 + c32 * 4) * 4,                     \
                   Mg + (size_t)((k0) + r) * SEQ + q0 + c32 * 4);              \
    }                                                                          \
} while (0)

    // ---- preamble: Q (into KV buf1) + mask0 (group A); KV0 (group B) ----
    {
        const uint32_t qb = sb + KVB2;
#pragma unroll
        for (int i = 0; i < 4; i++) {
            const int id = i * 256 + tid;
            const int r = id >> 4, c = id & 15;
            const size_t so = hoff + (size_t)r * SEQ + q0 + c * 8;
            CP_ASYNC16(qb + (uint32_t)(r * 272 + c * 16), Qf + so);
        }
    }
    A_CPMASK(0);
    CP_COMMIT();
    A_CPKV(0, 0);
    CP_COMMIT();
    CP_WAIT(1);
    __syncthreads();

    const int arow_k = (lane & 7) + ((lane >> 4) << 3);
    const int amcol  = ((lane >> 3) & 1) * 8;
    uint32_t qf[4][4];
#pragma unroll
    for (int ks = 0; ks < 4; ks++) {
        const uint32_t ao = (uint32_t)((ks * 16 + arow_k) * PKH + wid * 16 + amcol) * 2;
        LDSM_X4T(qf[ks][0], qf[ks][1], qf[ks][2], qf[ks][3], sb + KVB2 + ao);
    }
    __syncthreads();   // Q region free for KV buf1 (cp issued in tile 0)

    const int bj = lane >> 3, br = lane & 7;
    const int bk = (bj & 1) * 8 + br, bn8 = (bj >> 1) * 8;
    const int bvrow = ((lane >> 4) & 1) * 8 + br;
    const int bvk8  = ((lane >> 3) & 1) * 8;

    float o[8][4];
#pragma unroll
    for (int d = 0; d < 8; d++)
#pragma unroll
        for (int j = 0; j < 4; j++) o[d][j] = 0.f;
    float lsum0 = 0.f, lsum1 = 0.f;

    const int qr = wid * 16 + (lane >> 2);
    const int krow2 = 2 * (lane & 3);
    const float* Ms = (const float*)(sma + MASK_OFF);

    const int NT = SEQ / 128;
    for (int kt = 0; kt < NT; kt++) {
        CP_WAIT(0);
        __syncthreads();   // KV kt + mask kt resident; prior buf reads done

        const uint32_t kvb = sb + (kt & 1) * KVB2;

        // ---- mask (both halves) -> accumulator init ----
        float s[16][4];
#pragma unroll
        for (int nt = 0; nt < 16; nt++) {
            const float* mp = Ms + (nt * 8 + krow2) * 132 + qr;
            s[nt][0] = mp[0]   * LOG2E;
            s[nt][1] = mp[132] * LOG2E;
            s[nt][2] = mp[8]   * LOG2E;
            s[nt][3] = mp[140] * LOG2E;
        }
        __syncthreads();   // all warps consumed the mask buffer

        if (kt + 1 < NT) {
            A_CPKV((kt + 1) * 128, (kt + 1) & 1);
            A_CPMASK((kt + 1) * 128);
            CP_COMMIT();
        }

        // ---- QK mma (1-pass fp16), both halves (128 keys) ----
#pragma unroll
        for (int h2 = 0; h2 < 2; h2++)
#pragma unroll
            for (int ks = 0; ks < 4; ks++)
#pragma unroll
                for (int np = 0; np < 4; np++) {
                    uint32_t kf[4];
                    const uint32_t bo = (uint32_t)((ks * 16 + bk) * PKH
                                                   + h2 * 64 + np * 16 + bn8) * 2;
                    LDSM_X4T(kf[0], kf[1], kf[2], kf[3], kvb + bo);
#pragma unroll
                    for (int s2 = 0; s2 < 2; s2++)
                        mma16816f(s[h2 * 8 + np * 2 + s2], qf[ks], &kf[s2 * 2]);
                }

        // ---- per half: exp/sums, pack, PV ----
#pragma unroll
        for (int h2 = 0; h2 < 2; h2++) {
            float* sh = &s[h2 * 8][0];
            float rs0 = 0.f, rs1 = 0.f;
#pragma unroll
            for (int nt = 0; nt < 8; nt++) {
                float* sn = sh + nt * 4;
#pragma unroll
                for (int j = 0; j < 4; j++) EX2F(sn[j], sn[j]);
                rs0 += sn[0] + sn[1];
                rs1 += sn[2] + sn[3];
            }
            rs0 += __shfl_xor_sync(0xffffffffu, rs0, 1);
            rs0 += __shfl_xor_sync(0xffffffffu, rs0, 2);
            rs1 += __shfl_xor_sync(0xffffffffu, rs1, 1);
            rs1 += __shfl_xor_sync(0xffffffffu, rs1, 2);
            lsum0 += rs0;
            lsum1 += rs1;

            uint32_t pa[4][4];
#pragma unroll
            for (int ks = 0; ks < 4; ks++) {
                const float* u = sh + ks * 8;
                const float* w = sh + ks * 8 + 4;
                CVT_F16X2(pa[ks][0], u[0], u[1]);
                CVT_F16X2(pa[ks][1], u[2], u[3]);
                CVT_F16X2(pa[ks][2], w[0], w[1]);
                CVT_F16X2(pa[ks][3], w[2], w[3]);
            }
#pragma unroll
            for (int ks = 0; ks < 4; ks++)
#pragma unroll
                for (int dp = 0; dp < 4; dp++) {
                    uint32_t vf[4];
                    const uint32_t bo = (uint32_t)((dp * 16 + bvrow) * PKH
                                                   + h2 * 64 + ks * 16 + bvk8) * 2;
                    LDSM_X4(vf[0], vf[1], vf[2], vf[3], kvb + KVA + bo);
#pragma unroll
                    for (int s2 = 0; s2 < 2; s2++)
                        mma16816f(o[dp * 2 + s2], pa[ks], &vf[s2 * 2]);
                }
        }
    }

    // ---- normalize, transpose via smem, fp16-single coalesced store ----
    const float inv0 = 1.f / lsum0, inv1 = 1.f / lsum1;
    __syncthreads();
    float* Os = (float*)sma;
#pragma unroll
    for (int d = 0; d < 8; d++) {
        const int dc = d * 8 + krow2;
        Os[dc * 132 + qr]           = o[d][0] * inv0;
        Os[(dc + 1) * 132 + qr]     = o[d][1] * inv0;
        Os[dc * 132 + qr + 8]       = o[d][2] * inv1;
        Os[(dc + 1) * 132 + qr + 8] = o[d][3] * inv1;
    }
    __syncthreads();
#pragma unroll
    for (int i = 0; i < 8; i++) {
        const int e = i * 256 + tid;
        const int r = e >> 5, c4 = (e & 31) * 4;
        const float4 v = *(const float4*)&Os[r * 132 + c4];
        uint32_t f0, f1;
        CVT_F16X2(f0, v.x, v.y);
        CVT_F16X2(f1, v.z, v.w);
        *(uint2*)&Of[hoff + (size_t)r * SEQ + q0 + c4] = make_uint2(f0, f1);
    }
}

// ---------------------------------------------------------------------------
extern "C" void kernel_launch(void* const* d_in, const int* in_sizes, int n_in,
                              void* d_out, int out_size)
{
    const float* q   = (const float*)d_in[0];
    const float* k   = (const float*)d_in[1];
    const float* v   = (const float*)d_in[2];
    const float* msk = (const float*)d_in[3];
    const float* Wq  = (const float*)d_in[4];
    const float* bq  = (const float*)d_in[5];
    const float* Wk  = (const float*)d_in[6];
    const float* bk  = (const float*)d_in[7];
    const float* Wv  = (const float*)d_in[8];
    const float* bv  = (const float*)d_in[9];
    const float* Wo  = (const float*)d_in[10];
    const float* bo  = (const float*)d_in[11];
    float* out = (float*)d_out;

    void *pwh, *pwl, *pxf, *ppf, *patf;
    cudaGetSymbolAddress(&pwh, g_wh);
    cudaGetSymbolAddress(&pwl, g_wl);
    cudaGetSymbolAddress(&pxf, g_xf);
    cudaGetSymbolAddress(&ppf, g_pf);
    cudaGetSymbolAddress(&patf, g_atf);

    ushort_t* wh = (ushort_t*)pwh;  ushort_t* wl = (ushort_t*)pwl;
    ushort_t* xf = (ushort_t*)pxf;
    ushort_t* pf = (ushort_t*)ppf;
    ushort_t* atf = (ushort_t*)patf;

    cudaFuncSetAttribute(gemm_qkv, cudaFuncAttributeMaxDynamicSharedMemorySize, GB_SMEM);
    cudaFuncSetAttribute(gemm_wo,  cudaFuncAttributeMaxDynamicSharedMemorySize, GB_SMEM);
    cudaFuncSetAttribute(attn_mma, cudaFuncAttributeMaxDynamicSharedMemorySize, AT_SMEM);

    // 1. converts
    conv_w<<<dim3((unsigned)(WSZ / 1024), 4), 256>>>(Wq, Wk, Wv, Wo, wh, wl);
    conv_x<<<dim3((unsigned)(XSZ / 1024), 3), 256>>>(q, k, v, xf);

    // 2. merged QKV projections (all fp16-single out)
    dim3 gq(SEQ / 128, EMB / 128, 6);
    gemm_qkv<<<gq, 256, GB_SMEM>>>(wh, wl, xf, bq, bk, bv, pf);

    // 3. attention (1-pass QK, 1-pass PV)
    dim3 ga(SEQ / 128, NH, BATCH);
    attn_mma<<<ga, 256, AT_SMEM>>>(pf + 0 * XSZ, pf + 1 * XSZ, pf + 2 * XSZ,
                                   msk, atf);

    // 4. output projection
    dim3 go(SEQ / 128, EMB / 128, BATCH);
    gemm_wo<<<go, 256, GB_SMEM>>>(wh + 3 * WSZ, wl + 3 * WSZ, atf, bo, out);
}

// round 17
// speedup vs baseline: 1.4302x; 1.0965x over previous
#include <cuda_runtime.h>
#include <cuda_fp16.h>
#include <cstdint>

#define BATCH 2
#define EMB   1024
#define SEQ   2048
#define NH    16
#define DH    64
#define KDIM  1024
#define LOG2E 1.4426950408889634f
typedef unsigned short ushort_t;

#define WSZ ((size_t)KDIM * EMB)
#define XSZ ((size_t)BATCH * EMB * SEQ)
#define ESZ ((size_t)EMB * SEQ)

// ---------------- scratch ----------------------------------------------------
__device__ ushort_t g_wh[4 * WSZ];   // weights fp16-hi
__device__ ushort_t g_wl[4 * WSZ];   // weights fp16-lo (Wq, Wk only used)
__device__ ushort_t g_xf[3 * XSZ];   // q,k,v inputs fp16 single
__device__ ushort_t g_pf[3 * XSZ];   // Q, K, V projections fp16 single
__device__ ushort_t g_atf[XSZ];      // attn out fp16 single

// ---------------- helpers ----------------------------------------------------
__device__ __forceinline__ uint32_t smem_u32(const void* p) {
    uint32_t a;
    asm("{ .reg .u64 t; cvta.to.shared.u64 t, %1; cvt.u32.u64 %0, t; }" : "=r"(a) : "l"(p));
    return a;
}
__device__ __forceinline__ void mma16816f(float* c, const uint32_t* a, const uint32_t* b) {
    asm volatile("mma.sync.aligned.m16n8k16.row.col.f32.f16.f16.f32 "
        "{%0,%1,%2,%3}, {%4,%5,%6,%7}, {%8,%9}, {%0,%1,%2,%3};"
        : "+f"(c[0]), "+f"(c[1]), "+f"(c[2]), "+f"(c[3])
        : "r"(a[0]), "r"(a[1]), "r"(a[2]), "r"(a[3]), "r"(b[0]), "r"(b[1]));
}
#define LDSM_X4(r0,r1,r2,r3,addr) \
    asm volatile("ldmatrix.sync.aligned.m8n8.x4.shared.b16 {%0,%1,%2,%3}, [%4];" \
                 : "=r"(r0),"=r"(r1),"=r"(r2),"=r"(r3) : "r"(addr))
#define LDSM_X4T(r0,r1,r2,r3,addr) \
    asm volatile("ldmatrix.sync.aligned.m8n8.x4.trans.shared.b16 {%0,%1,%2,%3}, [%4];" \
                 : "=r"(r0),"=r"(r1),"=r"(r2),"=r"(r3) : "r"(addr))
#define CVT_F16X2(res,a,b)  asm("cvt.rn.f16x2.f32 %0, %1, %2;" : "=r"(res) : "f"(b), "f"(a))
#define EX2F(y,x) asm("ex2.approx.f32 %0, %1;" : "=f"(y) : "f"(x))
#define CP_ASYNC16(dst, src) \
    asm volatile("cp.async.cg.shared.global [%0], [%1], 16;" :: "r"(dst), "l"(src) : "memory")
#define CP_COMMIT() asm volatile("cp.async.commit_group;" ::: "memory")
#define CP_WAIT(n) asm volatile("cp.async.wait_group %0;" :: "n"(n) : "memory")

__device__ __forceinline__ void split4_f16(const float4 v, uint32_t& h0, uint32_t& h1,
                                           uint32_t& l0, uint32_t& l1) {
    CVT_F16X2(h0, v.x, v.y);
    CVT_F16X2(h1, v.z, v.w);
    const __half2 hx = *(const __half2*)&h0;
    const __half2 hy = *(const __half2*)&h1;
    const float r0 = v.x - __half2float(__low2half(hx));
    const float r1 = v.y - __half2float(__high2half(hx));
    const float r2 = v.z - __half2float(__low2half(hy));
    const float r3 = v.w - __half2float(__high2half(hy));
    CVT_F16X2(l0, r0, r1);
    CVT_F16X2(l1, r2, r3);
}

// ---------------- converts ----------------------------------------------------
__global__ void __launch_bounds__(256) conv_w(
    const float* __restrict__ w0, const float* __restrict__ w1,
    const float* __restrict__ w2, const float* __restrict__ w3,
    ushort_t* __restrict__ hi, ushort_t* __restrict__ lo)
{
    const int g = blockIdx.y;
    const float* src = g == 0 ? w0 : (g == 1 ? w1 : (g == 2 ? w2 : w3));
    const size_t i = ((size_t)blockIdx.x * 256 + threadIdx.x) * 4;
    const float4 v = *(const float4*)&src[i];
    uint32_t h0, h1, l0, l1;
    split4_f16(v, h0, h1, l0, l1);
    *(uint2*)&hi[g * WSZ + i] = make_uint2(h0, h1);
    *(uint2*)&lo[g * WSZ + i] = make_uint2(l0, l1);
}
__global__ void __launch_bounds__(256) conv_x(
    const float* __restrict__ x0, const float* __restrict__ x1,
    const float* __restrict__ x2, ushort_t* __restrict__ xf)
{
    const int g = blockIdx.y;
    const float* src = g == 0 ? x0 : (g == 1 ? x1 : x2);
    const size_t i = ((size_t)blockIdx.x * 256 + threadIdx.x) * 4;
    const float4 v = *(const float4*)&src[i];
    uint32_t f0, f1;
    CVT_F16X2(f0, v.x, v.y);
    CVT_F16X2(f1, v.z, v.w);
    *(uint2*)&xf[g * XSZ + i] = make_uint2(f0, f1);
}

// ---------------- GEMM body: fp16, 1 or 2 passes over W ----------------------
// mode: 0 = f32 out, 2 = fp16 single out
#define LAH 56
#define LBH 136
#define G_AH 0
#define G_AL 14336
#define G_BF 28672
#define G_BUF 37376
#define G_BIAS 74752
#define GB_SMEM 75264

__device__ __forceinline__ void gemm_body(
    const ushort_t* __restrict__ Ah, const ushort_t* __restrict__ Al,
    const ushort_t* __restrict__ Bf,
    const float* __restrict__ bias, float* __restrict__ Cf,
    ushort_t* __restrict__ Ch, float alpha, int mode, int passes)
{
    extern __shared__ char smg[];
    const uint32_t sb = smem_u32(smg);
    const int tid = threadIdx.x, wid = tid >> 5, lane = tid & 31;
    const int n0 = blockIdx.x * 128, m0 = blockIdx.y * 128;
    float* bias_s = (float*)(smg + G_BIAS);
    if (tid < 128) bias_s[tid] = bias[m0 + tid];

    const int wm = wid & 3, wn = wid >> 2;
    float acc[2][8][4];
#pragma unroll
    for (int ms = 0; ms < 2; ms++)
#pragma unroll
        for (int nt = 0; nt < 8; nt++)
#pragma unroll
            for (int i = 0; i < 4; i++) acc[ms][nt][i] = 0.f;

    const int arow = lane & 15, ak8 = (lane >> 4) * 8;
    const int bj = lane >> 3, br = lane & 7;
    const int bk = (bj & 1) * 8 + br, bn8 = (bj >> 1) * 8;

#define G_CP(kt, buf) do {                                                     \
    const uint32_t base = sb + (buf) * G_BUF;                                  \
    _Pragma("unroll")                                                          \
    for (int i = 0; i < 2; i++) {                                              \
        const int id = i * 256 + tid;                                          \
        const int r = id >> 2, c = id & 3;                                     \
        const size_t so = (size_t)(m0 + r) * KDIM + (kt) * 32 + c * 8;         \
        const uint32_t doff = (uint32_t)(r * 112 + c * 16);                    \
        CP_ASYNC16(base + G_AH + doff, Ah + so);                               \
        if (passes == 2) CP_ASYNC16(base + G_AL + doff, Al + so);              \
    }                                                                          \
    _Pragma("unroll")                                                          \
    for (int i = 0; i < 2; i++) {                                              \
        const int id = i * 256 + tid;                                          \
        const int r = id >> 4, c = id & 15;                                    \
        const size_t so = (size_t)((kt) * 32 + r) * SEQ + n0 + c * 8;          \
        const uint32_t doff = (uint32_t)(r * 272 + c * 16);                    \
        CP_ASYNC16(base + G_BF + doff, Bf + so);                               \
    }                                                                          \
} while (0)

    G_CP(0, 0);
    CP_COMMIT();

    const int NKT = KDIM / 32;
    for (int kt = 0; kt < NKT; kt++) {
        __syncthreads();
        if (kt + 1 < NKT) { G_CP(kt + 1, (kt + 1) & 1); CP_COMMIT(); CP_WAIT(1); }
        else CP_WAIT(0);
        __syncthreads();

        const uint32_t base = sb + (kt & 1) * G_BUF;
#pragma unroll
        for (int ks = 0; ks < 2; ks++) {
            uint32_t aF[2][4], aL[2][4];
#pragma unroll
            for (int ms = 0; ms < 2; ms++) {
                const uint32_t ao = (uint32_t)((wm * 32 + ms * 16 + arow) * LAH + ks * 16 + ak8) * 2;
                LDSM_X4(aF[ms][0], aF[ms][1], aF[ms][2], aF[ms][3], base + G_AH + ao);
                if (passes == 2)
                    LDSM_X4(aL[ms][0], aL[ms][1], aL[ms][2], aL[ms][3], base + G_AL + ao);
            }
#pragma unroll
            for (int nt16 = 0; nt16 < 4; nt16++) {
                uint32_t bF[4];
                const uint32_t bo = (uint32_t)((ks * 16 + bk) * LBH + wn * 64 + nt16 * 16 + bn8) * 2;
                LDSM_X4T(bF[0], bF[1], bF[2], bF[3], base + G_BF + bo);
#pragma unroll
                for (int ms = 0; ms < 2; ms++)
#pragma unroll
                    for (int s = 0; s < 2; s++) {
                        float* a4 = acc[ms][nt16 * 2 + s];
                        mma16816f(a4, aF[ms], &bF[s * 2]);
                        if (passes == 2) mma16816f(a4, aL[ms], &bF[s * 2]);
                    }
            }
        }
    }

    __syncthreads();
    float* Cs = (float*)smg;
    {
        const int rr = lane >> 2, cc = (lane & 3) * 2;
#pragma unroll
        for (int ms = 0; ms < 2; ms++)
#pragma unroll
            for (int nt = 0; nt < 8; nt++) {
                const int r = wm * 32 + ms * 16 + rr;
                const int c = wn * 64 + nt * 8 + cc;
                Cs[r * 132 + c]           = acc[ms][nt][0];
                Cs[r * 132 + c + 1]       = acc[ms][nt][1];
                Cs[(r + 8) * 132 + c]     = acc[ms][nt][2];
                Cs[(r + 8) * 132 + c + 1] = acc[ms][nt][3];
            }
    }
    __syncthreads();
#pragma unroll
    for (int i = 0; i < 16; i++) {
        const int e = i * 256 + tid;
        const int r = e >> 5, c4 = (e & 31) * 4;
        float4 v = *(const float4*)&Cs[r * 132 + c4];
        const float bi = bias_s[r];
        v.x = alpha * (v.x + bi); v.y = alpha * (v.y + bi);
        v.z = alpha * (v.z + bi); v.w = alpha * (v.w + bi);
        const size_t go = (size_t)(m0 + r) * SEQ + n0 + c4;
        if (mode == 0) {
            *(float4*)&Cf[go] = v;
        } else {
            uint32_t f0, f1;
            CVT_F16X2(f0, v.x, v.y);
            CVT_F16X2(f1, v.z, v.w);
            *(uint2*)&Ch[go] = make_uint2(f0, f1);
        }
    }
}

__global__ void __launch_bounds__(256, 2) gemm_qkv(
    const ushort_t* __restrict__ wh, const ushort_t* __restrict__ wl,
    const ushort_t* __restrict__ xf,
    const float* __restrict__ bq, const float* __restrict__ bk,
    const float* __restrict__ bv, ushort_t* __restrict__ pf)
{
    const int gi = blockIdx.z >> 1, bb = blockIdx.z & 1;
    const size_t woff = (size_t)gi * WSZ;
    const size_t xoff = (size_t)gi * XSZ + (size_t)bb * ESZ;
    const float* bias = gi == 0 ? bq : (gi == 1 ? bk : bv);
    const float alpha = gi == 0 ? 0.125f * LOG2E : 1.0f;
    const int passes = gi == 2 ? 1 : 2;   // V projection: W single-pass
    gemm_body(wh + woff, wl + woff, xf + xoff, bias,
              nullptr, pf + xoff, alpha, 2, passes);
}
__global__ void __launch_bounds__(256, 2) gemm_wo(
    const ushort_t* __restrict__ wh, const ushort_t* __restrict__ wl,
    const ushort_t* __restrict__ af,
    const float* __restrict__ bo, float* __restrict__ out)
{
    const size_t off = (size_t)blockIdx.z * ESZ;
    gemm_body(wh, wl, af + off, bo, out + off, nullptr, 1.0f, 0, 1);  // 1-pass
}

// ---------------- flash attention (unchanged from R16) -----------------------
#define PKH 136
#define KVA 17408            // one array (64 x 136 halves)
#define KVB2 34816           // buffer: Kf, Vf
#define MASK_OFF 69632       // 128 x 132 f32 = 67584 B
#define AT_SMEM 137216       // = MASK_OFF + 67584

__global__ void __launch_bounds__(256) attn_mma(
    const ushort_t* __restrict__ Qf,
    const ushort_t* __restrict__ Kf, const ushort_t* __restrict__ Vf,
    const float* __restrict__ MASK,
    ushort_t* __restrict__ Of)
{
    extern __shared__ char sma[];
    const uint32_t sb = smem_u32(sma);
    const int tid = threadIdx.x, wid = tid >> 5, lane = tid & 31;
    const int b = blockIdx.z, h = blockIdx.y, q0 = blockIdx.x * 128;

    const size_t hoff = ((size_t)b * EMB + h * DH) * SEQ;
    const float* Mg = MASK + (size_t)b * SEQ * SEQ;

#define A_CPKV(k0, buf) do {                                                   \
    const uint32_t base = sb + (buf) * KVB2;                                   \
    _Pragma("unroll")                                                          \
    for (int i = 0; i < 4; i++) {                                              \
        const int id = i * 256 + tid;                                          \
        const int r = id >> 4, c = id & 15;                                    \
        const size_t so = hoff + (size_t)r * SEQ + (k0) + c * 8;               \
        const uint32_t doff = (uint32_t)(r * 272 + c * 16);                    \
        CP_ASYNC16(base +       doff, Kf + so);                                \
        CP_ASYNC16(base + KVA + doff, Vf + so);                                \
    }                                                                          \
} while (0)

#define A_CPMASK(k0) do {                                                      \
    const uint32_t mb = sb + MASK_OFF;                                         \
    _Pragma("unroll")                                                          \
    for (int i = 0; i < 16; i++) {                                             \
        const int id = i * 256 + tid;                                          \
        const int r = id >> 5, c32 = id & 31;                                  \
        CP_ASYNC16(mb + (uint32_t)(r * 132 + c32 * 4) * 4,                     \
                   Mg + (size_t)((k0) + r) * SEQ + q0 + c32 * 4);              \
    }                                                                          \
} while (0)

    {
        const uint32_t qb = sb + KVB2;
#pragma unroll
        for (int i = 0; i < 4; i++) {
            const int id = i * 256 + tid;
            const int r = id >> 4, c = id & 15;
            const size_t so = hoff + (size_t)r * SEQ + q0 + c * 8;
            CP_ASYNC16(qb + (uint32_t)(r * 272 + c * 16), Qf + so);
        }
    }
    A_CPMASK(0);
    CP_COMMIT();
    A_CPKV(0, 0);
    CP_COMMIT();
    CP_WAIT(1);
    __syncthreads();

    const int arow_k = (lane & 7) + ((lane >> 4) << 3);
    const int amcol  = ((lane >> 3) & 1) * 8;
    uint32_t qf[4][4];
#pragma unroll
    for (int ks = 0; ks < 4; ks++) {
        const uint32_t ao = (uint32_t)((ks * 16 + arow_k) * PKH + wid * 16 + amcol) * 2;
        LDSM_X4T(qf[ks][0], qf[ks][1], qf[ks][2], qf[ks][3], sb + KVB2 + ao);
    }
    __syncthreads();

    const int bj = lane >> 3, br = lane & 7;
    const int bk = (bj & 1) * 8 + br, bn8 = (bj >> 1) * 8;
    const int bvrow = ((lane >> 4) & 1) * 8 + br;
    const int bvk8  = ((lane >> 3) & 1) * 8;

    float o[8][4];
#pragma unroll
    for (int d = 0; d < 8; d++)
#pragma unroll
        for (int j = 0; j < 4; j++) o[d][j] = 0.f;
    float lsum0 = 0.f, lsum1 = 0.f;

    const int qr = wid * 16 + (lane >> 2);
    const int krow2 = 2 * (lane & 3);
    const float* Ms = (const float*)(sma + MASK_OFF);

    const int NT = SEQ / 128;
    for (int kt = 0; kt < NT; kt++) {
        CP_WAIT(0);
        __syncthreads();

        const uint32_t kvb = sb + (kt & 1) * KVB2;

        float s[16][4];
#pragma unroll
        for (int nt = 0; nt < 16; nt++) {
            const float* mp = Ms + (nt * 8 + krow2) * 132 + qr;
            s[nt][0] = mp[0]   * LOG2E;
            s[nt][1] = mp[132] * LOG2E;
            s[nt][2] = mp[8]   * LOG2E;
            s[nt][3] = mp[140] * LOG2E;
        }
        __syncthreads();

        if (kt + 1 < NT) {
            A_CPKV((kt + 1) * 128, (kt + 1) & 1);
            A_CPMASK((kt + 1) * 128);
            CP_COMMIT();
        }

#pragma unroll
        for (int h2 = 0; h2 < 2; h2++)
#pragma unroll
            for (int ks = 0; ks < 4; ks++)
#pragma unroll
                for (int np = 0; np < 4; np++) {
                    uint32_t kf[4];
                    const uint32_t bo = (uint32_t)((ks * 16 + bk) * PKH
                                                   + h2 * 64 + np * 16 + bn8) * 2;
                    LDSM_X4T(kf[0], kf[1], kf[2], kf[3], kvb + bo);
#pragma unroll
                    for (int s2 = 0; s2 < 2; s2++)
                        mma16816f(s[h2 * 8 + np * 2 + s2], qf[ks], &kf[s2 * 2]);
                }

#pragma unroll
        for (int h2 = 0; h2 < 2; h2++) {
            float* sh = &s[h2 * 8][0];
            float rs0 = 0.f, rs1 = 0.f;
#pragma unroll
            for (int nt = 0; nt < 8; nt++) {
                float* sn = sh + nt * 4;
#pragma unroll
                for (int j = 0; j < 4; j++) EX2F(sn[j], sn[j]);
                rs0 += sn[0] + sn[1];
                rs1 += sn[2] + sn[3];
            }
            rs0 += __shfl_xor_sync(0xffffffffu, rs0, 1);
            rs0 += __shfl_xor_sync(0xffffffffu, rs0, 2);
            rs1 += __shfl_xor_sync(0xffffffffu, rs1, 1);
            rs1 += __shfl_xor_sync(0xffffffffu, rs1, 2);
            lsum0 += rs0;
            lsum1 += rs1;

            uint32_t pa[4][4];
#pragma unroll
            for (int ks = 0; ks < 4; ks++) {
                const float* u = sh + ks * 8;
                const float* w = sh + ks * 8 + 4;
                CVT_F16X2(pa[ks][0], u[0], u[1]);
                CVT_F16X2(pa[ks][1], u[2], u[3]);
                CVT_F16X2(pa[ks][2], w[0], w[1]);
                CVT_F16X2(pa[ks][3], w[2], w[3]);
            }
#pragma unroll
            for (int ks = 0; ks < 4; ks++)
#pragma unroll
                for (int dp = 0; dp < 4; dp++) {
                    uint32_t vf[4];
                    const uint32_t bo = (uint32_t)((dp * 16 + bvrow) * PKH
                                                   + h2 * 64 + ks * 16 + bvk8) * 2;
                    LDSM_X4(vf[0], vf[1], vf[2], vf[3], kvb + KVA + bo);
#pragma unroll
                    for (int s2 = 0; s2 < 2; s2++)
                        mma16816f(o[dp * 2 + s2], pa[ks], &vf[s2 * 2]);
                }
        }
    }

    const float inv0 = 1.f / lsum0, inv1 = 1.f / lsum1;
    __syncthreads();
    float* Os = (float*)sma;
#pragma unroll
    for (int d = 0; d < 8; d++) {
        const int dc = d * 8 + krow2;
        Os[dc * 132 + qr]           = o[d][0] * inv0;
        Os[(dc + 1) * 132 + qr]     = o[d][1] * inv0;
        Os[dc * 132 + qr + 8]       = o[d][2] * inv1;
        Os[(dc + 1) * 132 + qr + 8] = o[d][3] * inv1;
    }
    __syncthreads();
#pragma unroll
    for (int i = 0; i < 8; i++) {
        const int e = i * 256 + tid;
        const int r = e >> 5, c4 = (e & 31) * 4;
        const float4 v = *(const float4*)&Os[r * 132 + c4];
        uint32_t f0, f1;
        CVT_F16X2(f0, v.x, v.y);
        CVT_F16X2(f1, v.z, v.w);
        *(uint2*)&Of[hoff + (size_t)r * SEQ + q0 + c4] = make_uint2(f0, f1);
    }
}

// ---------------------------------------------------------------------------
extern "C" void kernel_launch(void* const* d_in, const int* in_sizes, int n_in,
                              void* d_out, int out_size)
{
    const float* q   = (const float*)d_in[0];
    const float* k   = (const float*)d_in[1];
    const float* v   = (const float*)d_in[2];
    const float* msk = (const float*)d_in[3];
    const float* Wq  = (const float*)d_in[4];
    const float* bq  = (const float*)d_in[5];
    const float* Wk  = (const float*)d_in[6];
    const float* bk  = (const float*)d_in[7];
    const float* Wv  = (const float*)d_in[8];
    const float* bv  = (const float*)d_in[9];
    const float* Wo  = (const float*)d_in[10];
    const float* bo  = (const float*)d_in[11];
    float* out = (float*)d_out;

    void *pwh, *pwl, *pxf, *ppf, *patf;
    cudaGetSymbolAddress(&pwh, g_wh);
    cudaGetSymbolAddress(&pwl, g_wl);
    cudaGetSymbolAddress(&pxf, g_xf);
    cudaGetSymbolAddress(&ppf, g_pf);
    cudaGetSymbolAddress(&patf, g_atf);

    ushort_t* wh = (ushort_t*)pwh;  ushort_t* wl = (ushort_t*)pwl;
    ushort_t* xf = (ushort_t*)pxf;
    ushort_t* pf = (ushort_t*)ppf;
    ushort_t* atf = (ushort_t*)patf;

    cudaFuncSetAttribute(gemm_qkv, cudaFuncAttributeMaxDynamicSharedMemorySize, GB_SMEM);
    cudaFuncSetAttribute(gemm_wo,  cudaFuncAttributeMaxDynamicSharedMemorySize, GB_SMEM);
    cudaFuncSetAttribute(attn_mma, cudaFuncAttributeMaxDynamicSharedMemorySize, AT_SMEM);

    // 1. converts
    conv_w<<<dim3((unsigned)(WSZ / 1024), 4), 256>>>(Wq, Wk, Wv, Wo, wh, wl);
    conv_x<<<dim3((unsigned)(XSZ / 1024), 3), 256>>>(q, k, v, xf);

    // 2. merged QKV projections (Q/K 2-pass, V 1-pass)
    dim3 gq(SEQ / 128, EMB / 128, 6);
    gemm_qkv<<<gq, 256, GB_SMEM>>>(wh, wl, xf, bq, bk, bv, pf);

    // 3. attention
    dim3 ga(SEQ / 128, NH, BATCH);
    attn_mma<<<ga, 256, AT_SMEM>>>(pf + 0 * XSZ, pf + 1 * XSZ, pf + 2 * XSZ,
                                   msk, atf);

    // 4. output projection (1-pass)
    dim3 go(SEQ / 128, EMB / 128, BATCH);
    gemm_wo<<<go, 256, GB_SMEM>>>(wh + 3 * WSZ, wl + 3 * WSZ, atf, bo, out);
}